// round 1
// baseline (speedup 1.0000x reference)
#include <cuda_runtime.h>
#include <cstdint>

#define BB   2
#define LL   2048
#define KNN  48
#define ED   128
#define EIN  416
#define NAT  5

// scratch (allocation-free rule: __device__ globals)
__device__ float g_atoms[BB * LL * NAT * 3];
__device__ int   g_eidx[BB * LL * KNN];

// ---------------------------------------------------------------------------
// Kernel 1: build atoms[Ca,N,C,O,Cb] per residue
// ---------------------------------------------------------------------------
__global__ void atoms_kernel(const float* __restrict__ X) {
    int idx = blockIdx.x * blockDim.x + threadIdx.x;
    if (idx >= BB * LL) return;
    const float* x = X + (size_t)idx * 12;
    float Nx = x[0],  Ny = x[1],  Nz = x[2];
    float Cax = x[3], Cay = x[4], Caz = x[5];
    float Cx = x[6],  Cy = x[7],  Cz = x[8];
    float Ox = x[9],  Oy = x[10], Oz = x[11];

    float bx = Cax - Nx,  by = Cay - Ny,  bz = Caz - Nz;   // bb = Ca - N
    float cx = Cx - Cax,  cy = Cy - Cay,  cz = Cz - Caz;   // cc = C - Ca
    float ax = by * cz - bz * cy;                          // aa = cross(bb, cc)
    float ay = bz * cx - bx * cz;
    float az = bx * cy - by * cx;
    float Cbx = -0.58273431f * ax + 0.56802827f * bx - 0.54067466f * cx + Cax;
    float Cby = -0.58273431f * ay + 0.56802827f * by - 0.54067466f * cy + Cay;
    float Cbz = -0.58273431f * az + 0.56802827f * bz - 0.54067466f * cz + Caz;

    float* o = g_atoms + (size_t)idx * 15;
    o[0]  = Cax; o[1]  = Cay; o[2]  = Caz;   // Ca
    o[3]  = Nx;  o[4]  = Ny;  o[5]  = Nz;    // N
    o[6]  = Cx;  o[7]  = Cy;  o[8]  = Cz;    // C
    o[9]  = Ox;  o[10] = Oy;  o[11] = Oz;    // O
    o[12] = Cbx; o[13] = Cby; o[14] = Cbz;   // Cb
}

// ---------------------------------------------------------------------------
// Kernel 2: top-K nearest neighbors per (b,i), exact jax.lax.top_k semantics
// (ascending distance, ties -> lower index). One block of 256 per row.
// ---------------------------------------------------------------------------
__global__ void __launch_bounds__(256) topk_kernel(const float* __restrict__ X,
                                                   const float* __restrict__ mask,
                                                   float* __restrict__ outI) {
    __shared__ float cxs[LL], cys[LL], czs[LL], mms[LL];
    __shared__ unsigned long long wred[8];
    __shared__ float wmaxs[8];
    __shared__ unsigned long long s_key;
    __shared__ float s_dmax;

    int b   = blockIdx.x >> 11;
    int i   = blockIdx.x & (LL - 1);
    int tid = threadIdx.x;
    int lane = tid & 31, wid = tid >> 5;

    for (int t = tid; t < LL; t += 256) {
        const float* p = X + ((size_t)(b * LL + t) * 4 + 1) * 3;   // Ca
        cxs[t] = p[0]; cys[t] = p[1]; czs[t] = p[2];
        mms[t] = mask[b * LL + t];
    }
    __syncthreads();

    float xi = cxs[i], yi = cys[i], zi = czs[i], mi = mms[i];
    float dv[8], m2v[8];
    float dmax = 0.0f;
#pragma unroll
    for (int u = 0; u < 8; u++) {
        int j = tid * 8 + u;
        // exact fp32 op order, no fma-contraction, IEEE sqrt (matches XLA)
        float dx = __fsub_rn(cxs[j], xi);
        float dy = __fsub_rn(cys[j], yi);
        float dz = __fsub_rn(czs[j], zi);
        float s  = __fadd_rn(__fadd_rn(__fmul_rn(dx, dx), __fmul_rn(dy, dy)),
                             __fmul_rn(dz, dz));
        float dd  = __fsqrt_rn(__fadd_rn(s, 1e-6f));
        float mij = __fmul_rn(mi, mms[j]);
        dv[u]  = __fmul_rn(mij, dd);
        m2v[u] = mij;
        dmax = fmaxf(dmax, dv[u]);
    }
#pragma unroll
    for (int off = 16; off > 0; off >>= 1)
        dmax = fmaxf(dmax, __shfl_xor_sync(0xffffffffu, dmax, off));
    if (lane == 0) wmaxs[wid] = dmax;
    __syncthreads();
    if (tid == 0) {
        float m = wmaxs[0];
        for (int w = 1; w < 8; w++) m = fmaxf(m, wmaxs[w]);
        s_dmax = m;
    }
    __syncthreads();
    float dmx = s_dmax;

    unsigned long long k[8];
#pragma unroll
    for (int u = 0; u < 8; u++) {
        float adj = __fadd_rn(dv[u], __fmul_rn(__fsub_rn(1.0f, m2v[u]), dmx));
        k[u] = ((unsigned long long)__float_as_uint(adj) << 32) |
               (unsigned)(tid * 8 + u);
    }
    // odd-even transposition sort of 8 keys (fully unrolled, static indices)
#pragma unroll
    for (int p = 0; p < 8; p++) {
#pragma unroll
        for (int c = 0; c < 7; c++) {
            if (((c & 1) == (p & 1)) && k[c] > k[c + 1]) {
                unsigned long long t = k[c]; k[c] = k[c + 1]; k[c + 1] = t;
            }
        }
    }

    const unsigned long long INFK = ~0ull;
    size_t base = (size_t)(b * LL + i) * KNN;
    for (int r = 0; r < KNN; r++) {
        unsigned long long v = k[0];
#pragma unroll
        for (int off = 16; off > 0; off >>= 1) {
            unsigned long long o = __shfl_down_sync(0xffffffffu, v, off);
            if (o < v) v = o;
        }
        if (lane == 0) wred[wid] = v;
        __syncthreads();
        if (tid == 0) {
            unsigned long long m = wred[0];
            for (int w = 1; w < 8; w++) if (wred[w] < m) m = wred[w];
            s_key = m;
        }
        __syncthreads();
        unsigned long long key = s_key;
        if (k[0] == key) {   // unique winner (index embedded in key)
#pragma unroll
            for (int c = 0; c < 7; c++) k[c] = k[c + 1];
            k[7] = INFK;
        }
        if (tid == 0) {
            int j = (int)(unsigned)(key & 0xffffffffull);
            g_eidx[base + r] = j;
            if (outI) outI[base + r] = (float)j;
        }
    }
}

// ---------------------------------------------------------------------------
// Kernel 3 (hot): fused feature build (pos + RBF) + GEMV(416x128) + LayerNorm
// One block per (b,i). 256 threads = 16x16; each thread owns 3 rows x 8 cols.
// ---------------------------------------------------------------------------
__device__ __forceinline__ void ln_store(float* __restrict__ acc, size_t node,
                                         int row, int tx,
                                         const float* __restrict__ gam,
                                         const float* __restrict__ bet,
                                         float* __restrict__ outE) {
    float s = 0.0f;
#pragma unroll
    for (int c = 0; c < 8; c++) s += acc[c];
#pragma unroll
    for (int off = 8; off > 0; off >>= 1)
        s += __shfl_xor_sync(0xffffffffu, s, off);
    float mean = s * (1.0f / 128.0f);
    float v = 0.0f;
#pragma unroll
    for (int c = 0; c < 8; c++) { float d = acc[c] - mean; v += d * d; }
#pragma unroll
    for (int off = 8; off > 0; off >>= 1)
        v += __shfl_xor_sync(0xffffffffu, v, off);
    float rs = rsqrtf(v * (1.0f / 128.0f) + 1e-5f);

    float out[8];
#pragma unroll
    for (int c = 0; c < 8; c++)
        out[c] = (acc[c] - mean) * rs * gam[tx * 8 + c] + bet[tx * 8 + c];
    float* dst = outE + ((node * KNN + row) * ED) + tx * 8;
    *(float4*)dst       = make_float4(out[0], out[1], out[2], out[3]);
    *(float4*)(dst + 4) = make_float4(out[4], out[5], out[6], out[7]);
}

__global__ void __launch_bounds__(256) edge_kernel(
    const int* __restrict__ ridx, const int* __restrict__ chain,
    const float* __restrict__ Wpos, const float* __restrict__ bpos,
    const float* __restrict__ Wedge, const float* __restrict__ gamma_,
    const float* __restrict__ beta_, float* __restrict__ outE) {
    extern __shared__ float sm[];
    float* Ein  = sm;                 // 48*416 floats
    float* Wbuf = sm + KNN * EIN;     // 32*128 floats

    __shared__ float satoms[15];
    __shared__ float natoms[KNN * 15];
    __shared__ float gam[ED], bet[ED];
    __shared__ float bposs[16];
    __shared__ int eidx_s[KNN];
    __shared__ int dcls[KNN];

    int b   = blockIdx.x >> 11;
    int i   = blockIdx.x & (LL - 1);
    int tid = threadIdx.x;
    int tx  = tid & 15, ty = tid >> 4;
    size_t node = (size_t)(b * LL + i);

    if (tid < ED) { gam[tid] = gamma_[tid]; bet[tid] = beta_[tid]; }
    if (tid < KNN) eidx_s[tid] = g_eidx[node * KNN + tid];
    if (tid >= ED && tid < ED + 15) satoms[tid - ED] = g_atoms[node * 15 + (tid - ED)];
    if (tid >= ED + 16 && tid < ED + 32) bposs[tid - ED - 16] = bpos[tid - ED - 16];
    __syncthreads();

    if (tid < KNN) {
        int j = eidx_s[tid];
        int off = ridx[node] - ridx[b * LL + j];
        int same = (chain[node] == chain[b * LL + j]);
        int d = off + 32;
        d = d < 0 ? 0 : (d > 64 ? 64 : d);
        dcls[tid] = same ? d : 65;
    }
    for (int t = tid; t < KNN * 15; t += 256) {
        int n = t / 15, c = t % 15;
        natoms[t] = g_atoms[(size_t)(b * LL + eidx_s[n]) * 15 + c];
    }
    __syncthreads();

    // positional features: Ein[n][0..15] = W_pos[dcls[n]] + b_pos
    for (int t = tid; t < KNN * 16; t += 256) {
        int n = t >> 4, c = t & 15;
        Ein[n * EIN + c] = Wpos[dcls[n] * 16 + c] + bposs[c];
    }
    // RBF features: Ein[n][16 + (a1*5+a2)*16 + r]
    for (int t = tid; t < KNN * 25; t += 256) {
        int n = t / 25, pr = t % 25;
        int a1 = pr / 5, a2 = pr % 5;
        float dx = satoms[a1 * 3 + 0] - natoms[n * 15 + a2 * 3 + 0];
        float dy = satoms[a1 * 3 + 1] - natoms[n * 15 + a2 * 3 + 1];
        float dz = satoms[a1 * 3 + 2] - natoms[n * 15 + a2 * 3 + 2];
        float Dp = sqrtf(dx * dx + dy * dy + dz * dz + 1e-6f);
        float* dst = Ein + n * EIN + 16 + pr * 16;
#pragma unroll
        for (int rr = 0; rr < 16; rr++) {
            float mu = 2.0f + (20.0f / 15.0f) * (float)rr;   // linspace(2,22,16)
            float z  = (Dp - mu) * 0.8f;                      // 1/sigma = 16/20
            dst[rr] = __expf(-z * z);
        }
    }

    // GEMM: C[48x128] = Ein[48x416] @ Wedge[416x128], W streamed in 32-row chunks
    float acc0[8], acc1[8], acc2[8];
#pragma unroll
    for (int c = 0; c < 8; c++) { acc0[c] = 0.f; acc1[c] = 0.f; acc2[c] = 0.f; }
    const float* A0 = Ein + (ty)      * EIN;
    const float* A1 = Ein + (ty + 16) * EIN;
    const float* A2 = Ein + (ty + 32) * EIN;

    for (int ch = 0; ch < 13; ch++) {
        __syncthreads();
        const float4* wg = (const float4*)(Wedge + (size_t)ch * 32 * ED);
        float4* wb = (float4*)Wbuf;
#pragma unroll
        for (int e = 0; e < 4; e++) wb[tid + e * 256] = wg[tid + e * 256];
        __syncthreads();
        int kb = ch * 32;
#pragma unroll 8
        for (int kk = 0; kk < 32; kk++) {
            const float* wr = Wbuf + kk * ED + tx * 8;
            float4 p = *(const float4*)wr;
            float4 q = *(const float4*)(wr + 4);
            float a0 = A0[kb + kk], a1 = A1[kb + kk], a2 = A2[kb + kk];
            acc0[0] = fmaf(a0, p.x, acc0[0]); acc0[1] = fmaf(a0, p.y, acc0[1]);
            acc0[2] = fmaf(a0, p.z, acc0[2]); acc0[3] = fmaf(a0, p.w, acc0[3]);
            acc0[4] = fmaf(a0, q.x, acc0[4]); acc0[5] = fmaf(a0, q.y, acc0[5]);
            acc0[6] = fmaf(a0, q.z, acc0[6]); acc0[7] = fmaf(a0, q.w, acc0[7]);
            acc1[0] = fmaf(a1, p.x, acc1[0]); acc1[1] = fmaf(a1, p.y, acc1[1]);
            acc1[2] = fmaf(a1, p.z, acc1[2]); acc1[3] = fmaf(a1, p.w, acc1[3]);
            acc1[4] = fmaf(a1, q.x, acc1[4]); acc1[5] = fmaf(a1, q.y, acc1[5]);
            acc1[6] = fmaf(a1, q.z, acc1[6]); acc1[7] = fmaf(a1, q.w, acc1[7]);
            acc2[0] = fmaf(a2, p.x, acc2[0]); acc2[1] = fmaf(a2, p.y, acc2[1]);
            acc2[2] = fmaf(a2, p.z, acc2[2]); acc2[3] = fmaf(a2, p.w, acc2[3]);
            acc2[4] = fmaf(a2, q.x, acc2[4]); acc2[5] = fmaf(a2, q.y, acc2[5]);
            acc2[6] = fmaf(a2, q.z, acc2[6]); acc2[7] = fmaf(a2, q.w, acc2[7]);
        }
    }

    ln_store(acc0, node, ty,      tx, gam, bet, outE);
    ln_store(acc1, node, ty + 16, tx, gam, bet, outE);
    ln_store(acc2, node, ty + 32, tx, gam, bet, outE);
}

// ---------------------------------------------------------------------------
extern "C" void kernel_launch(void* const* d_in, const int* in_sizes, int n_in,
                              void* d_out, int out_size) {
    const float* X     = (const float*)d_in[0];
    const float* mask  = (const float*)d_in[1];
    const int*   ridx  = (const int*)d_in[2];
    const int*   chain = (const int*)d_in[3];
    const float* Wpos  = (const float*)d_in[4];
    const float* bpos  = (const float*)d_in[5];
    const float* Wedge = (const float*)d_in[6];
    const float* gam   = (const float*)d_in[7];
    const float* bet   = (const float*)d_in[8];

    float* outE = (float*)d_out;
    size_t nE = (size_t)BB * LL * KNN * ED;
    float* outI = ((size_t)out_size > nE) ? (outE + nE) : nullptr;

    atoms_kernel<<<(BB * LL + 255) / 256, 256>>>(X);
    topk_kernel<<<BB * LL, 256>>>(X, mask, outI);

    static const size_t smemK3 = (size_t)(KNN * EIN + 32 * ED) * sizeof(float);
    cudaFuncSetAttribute(edge_kernel,
                         cudaFuncAttributeMaxDynamicSharedMemorySize,
                         (int)smemK3);
    edge_kernel<<<BB * LL, 256, smemK3>>>(ridx, chain, Wpos, bpos, Wedge,
                                          gam, bet, outE);
    (void)in_sizes; (void)n_in;
}

// round 2
// speedup vs baseline: 2.0986x; 2.0986x over previous
#include <cuda_runtime.h>
#include <cstdint>

#define BB   2
#define LL   2048
#define KNN  48
#define ED   128
#define EIN  416
#define NAT  5

#define EINP 420      // Ein smem row stride (words): gid*4+tg -> conflict-free
#define WP   136      // W smem row stride (words): 8*tg+gid -> conflict-free
#define CSP  132      // C staging row stride

// scratch (allocation-free rule: __device__ globals)
__device__ float g_atoms[BB * LL * NAT * 3];
__device__ int   g_eidx[BB * LL * KNN];

__device__ __forceinline__ unsigned f2tf(float x) {
    unsigned r;
    asm("cvt.rna.tf32.f32 %0, %1;" : "=r"(r) : "f"(x));
    return r;
}

#define MMA_TF32(d, a, b)                                                     \
    asm volatile(                                                             \
        "mma.sync.aligned.m16n8k8.row.col.f32.tf32.tf32.f32 "                 \
        "{%0,%1,%2,%3}, {%4,%5,%6,%7}, {%8,%9}, {%0,%1,%2,%3};"               \
        : "+f"(d[0]), "+f"(d[1]), "+f"(d[2]), "+f"(d[3])                      \
        : "r"(a[0]), "r"(a[1]), "r"(a[2]), "r"(a[3]), "r"(b[0]), "r"(b[1]))

// ---------------------------------------------------------------------------
// Kernel 1: build atoms[Ca,N,C,O,Cb] per residue
// ---------------------------------------------------------------------------
__global__ void atoms_kernel(const float* __restrict__ X) {
    int idx = blockIdx.x * blockDim.x + threadIdx.x;
    if (idx >= BB * LL) return;
    const float* x = X + (size_t)idx * 12;
    float Nx = x[0],  Ny = x[1],  Nz = x[2];
    float Cax = x[3], Cay = x[4], Caz = x[5];
    float Cx = x[6],  Cy = x[7],  Cz = x[8];
    float Ox = x[9],  Oy = x[10], Oz = x[11];

    float bx = Cax - Nx,  by = Cay - Ny,  bz = Caz - Nz;
    float cx = Cx - Cax,  cy = Cy - Cay,  cz = Cz - Caz;
    float ax = by * cz - bz * cy;
    float ay = bz * cx - bx * cz;
    float az = bx * cy - by * cx;
    float Cbx = -0.58273431f * ax + 0.56802827f * bx - 0.54067466f * cx + Cax;
    float Cby = -0.58273431f * ay + 0.56802827f * by - 0.54067466f * cy + Cay;
    float Cbz = -0.58273431f * az + 0.56802827f * bz - 0.54067466f * cz + Caz;

    float* o = g_atoms + (size_t)idx * 15;
    o[0]  = Cax; o[1]  = Cay; o[2]  = Caz;
    o[3]  = Nx;  o[4]  = Ny;  o[5]  = Nz;
    o[6]  = Cx;  o[7]  = Cy;  o[8]  = Cz;
    o[9]  = Ox;  o[10] = Oy;  o[11] = Oz;
    o[12] = Cbx; o[13] = Cby; o[14] = Cbz;
}

// ---------------------------------------------------------------------------
// Kernel 2: top-K nearest neighbors. Warp-local selection + single-warp merge.
// Exact jax.lax.top_k semantics (ascending, ties -> lower index).
// ---------------------------------------------------------------------------
__global__ void __launch_bounds__(256) topk_kernel(const float* __restrict__ X,
                                                   const float* __restrict__ mask,
                                                   float* __restrict__ outI) {
    __shared__ float cxs[LL], cys[LL], czs[LL], mms[LL];
    __shared__ float wmaxs[8];
    __shared__ float s_dmax;
    __shared__ unsigned long long cand[8 * KNN];

    int b   = blockIdx.x >> 11;
    int i   = blockIdx.x & (LL - 1);
    int tid = threadIdx.x;
    int lane = tid & 31, wid = tid >> 5;

    for (int t = tid; t < LL; t += 256) {
        const float* p = X + ((size_t)(b * LL + t) * 4 + 1) * 3;   // Ca
        cxs[t] = p[0]; cys[t] = p[1]; czs[t] = p[2];
        mms[t] = mask[b * LL + t];
    }
    __syncthreads();

    float xi = cxs[i], yi = cys[i], zi = czs[i], mi = mms[i];
    float dv[8], m2v[8];
    float dmax = 0.0f;
#pragma unroll
    for (int u = 0; u < 8; u++) {
        int j = tid * 8 + u;
        // exact fp32 op order, no fma-contraction, IEEE sqrt (matches XLA)
        float dx = __fsub_rn(cxs[j], xi);
        float dy = __fsub_rn(cys[j], yi);
        float dz = __fsub_rn(czs[j], zi);
        float s  = __fadd_rn(__fadd_rn(__fmul_rn(dx, dx), __fmul_rn(dy, dy)),
                             __fmul_rn(dz, dz));
        float dd  = __fsqrt_rn(__fadd_rn(s, 1e-6f));
        float mij = __fmul_rn(mi, mms[j]);
        dv[u]  = __fmul_rn(mij, dd);
        m2v[u] = mij;
        dmax = fmaxf(dmax, dv[u]);
    }
#pragma unroll
    for (int off = 16; off > 0; off >>= 1)
        dmax = fmaxf(dmax, __shfl_xor_sync(0xffffffffu, dmax, off));
    if (lane == 0) wmaxs[wid] = dmax;
    __syncthreads();
    if (tid == 0) {
        float m = wmaxs[0];
        for (int w = 1; w < 8; w++) m = fmaxf(m, wmaxs[w]);
        s_dmax = m;
    }
    __syncthreads();
    float dmx = s_dmax;

    unsigned long long k[8];
#pragma unroll
    for (int u = 0; u < 8; u++) {
        float adj = __fadd_rn(dv[u], __fmul_rn(__fsub_rn(1.0f, m2v[u]), dmx));
        k[u] = ((unsigned long long)__float_as_uint(adj) << 32) |
               (unsigned)(tid * 8 + u);
    }
    // odd-even transposition sort of the per-thread 8 keys
#pragma unroll
    for (int p = 0; p < 8; p++) {
#pragma unroll
        for (int c = 0; c < 7; c++) {
            if (((c & 1) == (p & 1)) && k[c] > k[c + 1]) {
                unsigned long long t = k[c]; k[c] = k[c + 1]; k[c + 1] = t;
            }
        }
    }

    const unsigned long long INFK = ~0ull;
    // phase 1: per-warp top-48 (shfl only, no barriers)
    for (int r = 0; r < KNN; r++) {
        unsigned long long v = k[0];
#pragma unroll
        for (int off = 16; off > 0; off >>= 1) {
            unsigned long long o = __shfl_xor_sync(0xffffffffu, v, off);
            if (o < v) v = o;
        }
        if (k[0] == v) {   // unique winner pops its head
#pragma unroll
            for (int c = 0; c < 7; c++) k[c] = k[c + 1];
            k[7] = INFK;
        }
        if (lane == 0) cand[wid * KNN + r] = v;
    }
    __syncthreads();

    // phase 2: warp 0 merges 8 sorted streams of 48 -> global top-48
    if (wid == 0) {
        int ptr = 0;
        size_t base = (size_t)(b * LL + i) * KNN;
        for (int r = 0; r < KNN; r++) {
            unsigned long long key = (lane < 8) ? cand[lane * KNN + ptr] : INFK;
            unsigned long long m = key;
#pragma unroll
            for (int off = 16; off > 0; off >>= 1) {
                unsigned long long o = __shfl_xor_sync(0xffffffffu, m, off);
                if (o < m) m = o;
            }
            if (lane < 8 && key == m) ptr++;
            if (lane == 0) {
                int j = (int)(unsigned)(m & 0xffffffffull);
                g_eidx[base + r] = j;
                if (outI) outI[base + r] = (float)j;
            }
        }
    }
}

// ---------------------------------------------------------------------------
// Kernel 3 (hot): fused features + tf32 tensor-core GEMM (48x416 @ 416x128)
// + LayerNorm. One block per (b,i), 256 threads = 8 warps.
// Warp w owns C columns [16w, 16w+16); 3 row tiles x 2 col tiles of m16n8k8.
// ---------------------------------------------------------------------------
__global__ void __launch_bounds__(256, 2) edge_kernel(
    const int* __restrict__ ridx, const int* __restrict__ chain,
    const float* __restrict__ Wpos, const float* __restrict__ bpos,
    const float* __restrict__ Wedge, const float* __restrict__ gamma_,
    const float* __restrict__ beta_, float* __restrict__ outE) {
    extern __shared__ unsigned sm_u[];
    unsigned* EinU  = sm_u;                 // 48*EINP tf32 words
    unsigned* WbufU = sm_u + KNN * EINP;    // 32*WP tf32 words
    float*    Csm   = (float*)sm_u;         // aliases Ein region after k-loop

    __shared__ float satoms[15];
    __shared__ float natoms[KNN * 15];
    __shared__ float gam[ED], bet[ED];
    __shared__ float bposs[16];
    __shared__ int eidx_s[KNN];
    __shared__ int dcls[KNN];

    int b   = blockIdx.x >> 11;
    int i   = blockIdx.x & (LL - 1);
    int tid = threadIdx.x;
    int lane = tid & 31, w = tid >> 5;
    int gid = lane >> 2, tg = lane & 3;
    size_t node = (size_t)(b * LL + i);

    if (tid < ED) { gam[tid] = gamma_[tid]; bet[tid] = beta_[tid]; }
    if (tid < KNN) eidx_s[tid] = g_eidx[node * KNN + tid];
    if (tid >= ED && tid < ED + 15) satoms[tid - ED] = g_atoms[node * 15 + (tid - ED)];
    if (tid >= ED + 16 && tid < ED + 32) bposs[tid - ED - 16] = bpos[tid - ED - 16];
    __syncthreads();

    if (tid < KNN) {
        int j = eidx_s[tid];
        int off = ridx[node] - ridx[b * LL + j];
        int same = (chain[node] == chain[b * LL + j]);
        int d = off + 32;
        d = d < 0 ? 0 : (d > 64 ? 64 : d);
        dcls[tid] = same ? d : 65;
    }
    for (int t = tid; t < KNN * 15; t += 256) {
        int n = t / 15, c = t % 15;
        natoms[t] = g_atoms[(size_t)(b * LL + eidx_s[n]) * 15 + c];
    }
    __syncthreads();

    // positional features
    for (int t = tid; t < KNN * 16; t += 256) {
        int n = t >> 4, c = t & 15;
        EinU[n * EINP + c] = f2tf(Wpos[dcls[n] * 16 + c] + bposs[c]);
    }
    // RBF features
    for (int t = tid; t < KNN * 25; t += 256) {
        int n = t / 25, pr = t % 25;
        int a1 = pr / 5, a2 = pr % 5;
        float dx = satoms[a1 * 3 + 0] - natoms[n * 15 + a2 * 3 + 0];
        float dy = satoms[a1 * 3 + 1] - natoms[n * 15 + a2 * 3 + 1];
        float dz = satoms[a1 * 3 + 2] - natoms[n * 15 + a2 * 3 + 2];
        float Dp = sqrtf(dx * dx + dy * dy + dz * dz + 1e-6f);
        unsigned* dst = EinU + n * EINP + 16 + pr * 16;
#pragma unroll
        for (int rr = 0; rr < 16; rr++) {
            float mu = 2.0f + (20.0f / 15.0f) * (float)rr;
            float z  = (Dp - mu) * 0.8f;
            dst[rr] = f2tf(__expf(-z * z));
        }
    }

    // ---- tf32 MMA: C[48x128] = Ein @ Wedge, W streamed in 32-k chunks ----
    float acc[6][4];
#pragma unroll
    for (int t = 0; t < 6; t++)
#pragma unroll
        for (int c = 0; c < 4; c++) acc[t][c] = 0.0f;

    for (int ch = 0; ch < 13; ch++) {
        __syncthreads();
        const float4* wg = (const float4*)(Wedge + (size_t)ch * 32 * ED);
        for (int t = tid; t < 32 * 32; t += 256) {
            int row = t >> 5, c4 = t & 31;
            float4 v = wg[row * 32 + c4];
            uint4 u = make_uint4(f2tf(v.x), f2tf(v.y), f2tf(v.z), f2tf(v.w));
            *(uint4*)(WbufU + row * WP + c4 * 4) = u;
        }
        __syncthreads();
#pragma unroll
        for (int s = 0; s < 4; s++) {
            int kb = ch * 32 + s * 8;
            unsigned a[3][4];
#pragma unroll
            for (int t = 0; t < 3; t++) {
                int r = 16 * t + gid;
                a[t][0] = EinU[r * EINP + kb + tg];
                a[t][1] = EinU[(r + 8) * EINP + kb + tg];
                a[t][2] = EinU[r * EINP + kb + tg + 4];
                a[t][3] = EinU[(r + 8) * EINP + kb + tg + 4];
            }
            unsigned bf[2][2];
            int cb = w * 16;
#pragma unroll
            for (int j = 0; j < 2; j++) {
                bf[j][0] = WbufU[(s * 8 + tg) * WP + cb + 8 * j + gid];
                bf[j][1] = WbufU[(s * 8 + tg + 4) * WP + cb + 8 * j + gid];
            }
#pragma unroll
            for (int t = 0; t < 3; t++)
#pragma unroll
                for (int j = 0; j < 2; j++)
                    MMA_TF32(acc[t * 2 + j], a[t], bf[j]);
        }
    }

    // ---- stage C to smem (aliases Ein region) ----
    __syncthreads();
#pragma unroll
    for (int t = 0; t < 3; t++)
#pragma unroll
        for (int j = 0; j < 2; j++) {
            int row = 16 * t + gid;
            int col = w * 16 + 8 * j + 2 * tg;
            *(float2*)&Csm[row * CSP + col] =
                make_float2(acc[t * 2 + j][0], acc[t * 2 + j][1]);
            *(float2*)&Csm[(row + 8) * CSP + col] =
                make_float2(acc[t * 2 + j][2], acc[t * 2 + j][3]);
        }
    __syncthreads();

    // ---- LayerNorm + store: tx owns 8 cols, rows {ty, ty+16, ty+32} ----
    int tx = tid & 15, ty = tid >> 4;
#pragma unroll
    for (int rr = 0; rr < 3; rr++) {
        int row = ty + 16 * rr;
        float v8[8];
#pragma unroll
        for (int c = 0; c < 8; c++) v8[c] = Csm[row * CSP + tx * 8 + c];
        float s = 0.0f;
#pragma unroll
        for (int c = 0; c < 8; c++) s += v8[c];
#pragma unroll
        for (int off = 8; off > 0; off >>= 1)
            s += __shfl_xor_sync(0xffffffffu, s, off);
        float mean = s * (1.0f / 128.0f);
        float var = 0.0f;
#pragma unroll
        for (int c = 0; c < 8; c++) { float d = v8[c] - mean; var += d * d; }
#pragma unroll
        for (int off = 8; off > 0; off >>= 1)
            var += __shfl_xor_sync(0xffffffffu, var, off);
        float rs = rsqrtf(var * (1.0f / 128.0f) + 1e-5f);
        float out[8];
#pragma unroll
        for (int c = 0; c < 8; c++)
            out[c] = (v8[c] - mean) * rs * gam[tx * 8 + c] + bet[tx * 8 + c];
        float* dst = outE + ((node * KNN + row) * ED) + tx * 8;
        *(float4*)dst       = make_float4(out[0], out[1], out[2], out[3]);
        *(float4*)(dst + 4) = make_float4(out[4], out[5], out[6], out[7]);
    }
}

// ---------------------------------------------------------------------------
extern "C" void kernel_launch(void* const* d_in, const int* in_sizes, int n_in,
                              void* d_out, int out_size) {
    const float* X     = (const float*)d_in[0];
    const float* mask  = (const float*)d_in[1];
    const int*   ridx  = (const int*)d_in[2];
    const int*   chain = (const int*)d_in[3];
    const float* Wpos  = (const float*)d_in[4];
    const float* bpos  = (const float*)d_in[5];
    const float* Wedge = (const float*)d_in[6];
    const float* gam   = (const float*)d_in[7];
    const float* bet   = (const float*)d_in[8];

    float* outE = (float*)d_out;
    size_t nE = (size_t)BB * LL * KNN * ED;
    float* outI = ((size_t)out_size > nE) ? (outE + nE) : nullptr;

    atoms_kernel<<<(BB * LL + 255) / 256, 256>>>(X);
    topk_kernel<<<BB * LL, 256>>>(X, mask, outI);

    static const size_t smemK3 =
        (size_t)(KNN * EINP + 32 * WP) * sizeof(unsigned);
    cudaFuncSetAttribute(edge_kernel,
                         cudaFuncAttributeMaxDynamicSharedMemorySize,
                         (int)smemK3);
    edge_kernel<<<BB * LL, 256, smemK3>>>(ridx, chain, Wpos, bpos, Wedge,
                                          gam, bet, outE);
    (void)in_sizes; (void)n_in;
}

// round 5
// speedup vs baseline: 2.9599x; 1.4104x over previous
#include <cuda_runtime.h>
#include <cstdint>

#define BB   2
#define LL   2048
#define KNN  48
#define ED   128
#define NCH  13            // 13 K-chunks of 32 fp32 cols = K=416

#define ASTR 36            // A smem row stride (u32 words) -> conflict-free frags
#define WSTR 132           // W smem row stride (u32 words) -> conflict-free frags
#define AWRD (96 * ASTR)   // words per A stage = 3456
#define WWRD (32 * WSTR)   // words per W stage = 4224

// scratch (allocation-free rule: __device__ globals)
__device__ float    g_atoms[BB * LL * 15];
__device__ int      g_eidx[BB * LL * KNN];
__device__ unsigned g_Wt[416 * ED];   // W tf32-rounded bits, layout [k][n]

__device__ __forceinline__ unsigned f2tf(float x) {
    unsigned r;
    asm("cvt.rna.tf32.f32 %0, %1;" : "=r"(r) : "f"(x));
    return r;
}
__device__ __forceinline__ unsigned smem_u32(const void* p) {
    unsigned a;
    asm("{ .reg .u64 t; cvta.to.shared.u64 t, %1; cvt.u32.u64 %0, t; }"
        : "=r"(a) : "l"(p));
    return a;
}
__device__ __forceinline__ void cp16(unsigned dst, const void* src) {
    asm volatile("cp.async.cg.shared.global [%0], [%1], 16;" :: "r"(dst), "l"(src));
}
__device__ __forceinline__ void cp_commit() {
    asm volatile("cp.async.commit_group;" ::: "memory");
}
__device__ __forceinline__ void cp_wait2() {
    asm volatile("cp.async.wait_group 2;" ::: "memory");
}

#define MMA_TF32(d, a, b)                                                     \
    asm volatile(                                                             \
        "mma.sync.aligned.m16n8k8.row.col.f32.tf32.tf32.f32 "                 \
        "{%0,%1,%2,%3}, {%4,%5,%6,%7}, {%8,%9}, {%0,%1,%2,%3};"               \
        : "+f"(d[0]), "+f"(d[1]), "+f"(d[2]), "+f"(d[3])                      \
        : "r"(a[0]), "r"(a[1]), "r"(a[2]), "r"(a[3]), "r"(b[0]), "r"(b[1]))

// ---------------------------------------------------------------------------
// Kernel 0: pre-round W to tf32 bits (same [k][n] layout)
// ---------------------------------------------------------------------------
__global__ void wt_kernel(const float* __restrict__ W) {
    int idx = blockIdx.x * blockDim.x + threadIdx.x;
    if (idx < 416 * ED) g_Wt[idx] = f2tf(W[idx]);
}

// ---------------------------------------------------------------------------
// Kernel 1: build atoms[Ca,N,C,O,Cb] per residue
// ---------------------------------------------------------------------------
__global__ void atoms_kernel(const float* __restrict__ X) {
    int idx = blockIdx.x * blockDim.x + threadIdx.x;
    if (idx >= BB * LL) return;
    const float* x = X + (size_t)idx * 12;
    float Nx = x[0],  Ny = x[1],  Nz = x[2];
    float Cax = x[3], Cay = x[4], Caz = x[5];
    float Cx = x[6],  Cy = x[7],  Cz = x[8];
    float Ox = x[9],  Oy = x[10], Oz = x[11];

    float bx = Cax - Nx,  by = Cay - Ny,  bz = Caz - Nz;
    float cx = Cx - Cax,  cy = Cy - Cay,  cz = Cz - Caz;
    float ax = by * cz - bz * cy;
    float ay = bz * cx - bx * cz;
    float az = bx * cy - by * cx;
    float Cbx = -0.58273431f * ax + 0.56802827f * bx - 0.54067466f * cx + Cax;
    float Cby = -0.58273431f * ay + 0.56802827f * by - 0.54067466f * cy + Cay;
    float Cbz = -0.58273431f * az + 0.56802827f * bz - 0.54067466f * cz + Caz;

    float* o = g_atoms + (size_t)idx * 15;
    o[0]  = Cax; o[1]  = Cay; o[2]  = Caz;
    o[3]  = Nx;  o[4]  = Ny;  o[5]  = Nz;
    o[6]  = Cx;  o[7]  = Cy;  o[8]  = Cz;
    o[9]  = Ox;  o[10] = Oy;  o[11] = Oz;
    o[12] = Cbx; o[13] = Cby; o[14] = Cbz;
}

// ---------------------------------------------------------------------------
// Kernel 2: top-K nearest neighbors (exact jax.lax.top_k semantics)
// ---------------------------------------------------------------------------
__global__ void __launch_bounds__(256) topk_kernel(const float* __restrict__ X,
                                                   const float* __restrict__ mask,
                                                   float* __restrict__ outI) {
    __shared__ float cxs[LL], cys[LL], czs[LL], mms[LL];
    __shared__ float wmaxs[8];
    __shared__ float s_dmax;
    __shared__ unsigned long long cand[8 * KNN];

    int b   = blockIdx.x >> 11;
    int i   = blockIdx.x & (LL - 1);
    int tid = threadIdx.x;
    int lane = tid & 31, wid = tid >> 5;

    for (int t = tid; t < LL; t += 256) {
        const float* p = X + ((size_t)(b * LL + t) * 4 + 1) * 3;   // Ca
        cxs[t] = p[0]; cys[t] = p[1]; czs[t] = p[2];
        mms[t] = mask[b * LL + t];
    }
    __syncthreads();

    float xi = cxs[i], yi = cys[i], zi = czs[i], mi = mms[i];
    float dv[8], m2v[8];
    float dmax = 0.0f;
#pragma unroll
    for (int u = 0; u < 8; u++) {
        int j = tid * 8 + u;
        float dx = __fsub_rn(cxs[j], xi);
        float dy = __fsub_rn(cys[j], yi);
        float dz = __fsub_rn(czs[j], zi);
        float s  = __fadd_rn(__fadd_rn(__fmul_rn(dx, dx), __fmul_rn(dy, dy)),
                             __fmul_rn(dz, dz));
        float dd  = __fsqrt_rn(__fadd_rn(s, 1e-6f));
        float mij = __fmul_rn(mi, mms[j]);
        dv[u]  = __fmul_rn(mij, dd);
        m2v[u] = mij;
        dmax = fmaxf(dmax, dv[u]);
    }
#pragma unroll
    for (int off = 16; off > 0; off >>= 1)
        dmax = fmaxf(dmax, __shfl_xor_sync(0xffffffffu, dmax, off));
    if (lane == 0) wmaxs[wid] = dmax;
    __syncthreads();
    if (tid == 0) {
        float m = wmaxs[0];
        for (int w = 1; w < 8; w++) m = fmaxf(m, wmaxs[w]);
        s_dmax = m;
    }
    __syncthreads();
    float dmx = s_dmax;

    unsigned long long k[8];
#pragma unroll
    for (int u = 0; u < 8; u++) {
        float adj = __fadd_rn(dv[u], __fmul_rn(__fsub_rn(1.0f, m2v[u]), dmx));
        k[u] = ((unsigned long long)__float_as_uint(adj) << 32) |
               (unsigned)(tid * 8 + u);
    }
#pragma unroll
    for (int p = 0; p < 8; p++) {
#pragma unroll
        for (int c = 0; c < 7; c++) {
            if (((c & 1) == (p & 1)) && k[c] > k[c + 1]) {
                unsigned long long t = k[c]; k[c] = k[c + 1]; k[c + 1] = t;
            }
        }
    }

    const unsigned long long INFK = ~0ull;
    for (int r = 0; r < KNN; r++) {
        unsigned long long v = k[0];
#pragma unroll
        for (int off = 16; off > 0; off >>= 1) {
            unsigned long long o = __shfl_xor_sync(0xffffffffu, v, off);
            if (o < v) v = o;
        }
        if (k[0] == v) {
#pragma unroll
            for (int c = 0; c < 7; c++) k[c] = k[c + 1];
            k[7] = INFK;
        }
        if (lane == 0) cand[wid * KNN + r] = v;
    }
    __syncthreads();

    if (wid == 0) {
        int ptr = 0;
        size_t base = (size_t)(b * LL + i) * KNN;
        for (int r = 0; r < KNN; r++) {
            unsigned long long key = (lane < 8) ? cand[lane * KNN + ptr] : INFK;
            unsigned long long m = key;
#pragma unroll
            for (int off = 16; off > 0; off >>= 1) {
                unsigned long long o = __shfl_xor_sync(0xffffffffu, m, off);
                if (o < m) m = o;
            }
            if (lane < 8 && key == m) ptr++;
            if (lane == 0) {
                int j = (int)(unsigned)(m & 0xffffffffull);
                g_eidx[base + r] = j;
                if (outI) outI[base + r] = (float)j;
            }
        }
    }
}

// ---------------------------------------------------------------------------
// Kernel 3 (hot): 2 nodes per CTA (96x128 tile). Feature chunks (double-buf)
// + pre-tf32 W via 4-stage cp.async ring + mma.sync tf32 + fused LayerNorm.
// 8 warps: warp = 48 rows x 32 cols (rg = wid>>2, cg = wid&3).
// dynamic smem: A[2][96*36]u32 + W[4][32*132]u32 = 95232 B.
// ---------------------------------------------------------------------------
__global__ void __launch_bounds__(256, 2) edge_kernel(
    const int* __restrict__ ridx, const int* __restrict__ chain,
    const float* __restrict__ Wpos, const float* __restrict__ bpos,
    const float* __restrict__ gamma_, const float* __restrict__ beta_,
    float* __restrict__ outE) {
    extern __shared__ unsigned dsm[];
    __shared__ float ssat[2 * 15];
    __shared__ float snat[96 * 15];
    __shared__ float gam[ED], bet[ED];
    __shared__ float bposs[16];
    __shared__ int   eidx_s[96];
    __shared__ int   dcls[96];

    int tid  = threadIdx.x;
    int wid  = tid >> 5;
    int lane = tid & 31;
    int gid  = lane >> 2, tg = lane & 3;
    int node0 = 2 * blockIdx.x;
    int b = node0 >> 11;

    unsigned smW = smem_u32(dsm) + 2 * AWRD * 4;

    if (tid < ED) { gam[tid] = gamma_[tid]; bet[tid] = beta_[tid]; }
    if (tid < 16) bposs[tid] = bpos[tid];
    if (tid < 96) eidx_s[tid] = g_eidx[(size_t)node0 * KNN + tid];
    if (tid >= 128 && tid < 158) ssat[tid - 128] = g_atoms[(size_t)node0 * 15 + (tid - 128)];
    __syncthreads();

    if (tid < 96) {
        int nl = tid / KNN;
        int j  = eidx_s[tid];
        int ng = node0 + nl;
        int off  = ridx[ng] - ridx[b * LL + j];
        int same = (chain[ng] == chain[b * LL + j]);
        int d = off + 32;
        d = d < 0 ? 0 : (d > 64 ? 64 : d);
        dcls[tid] = same ? d : 65;
    }
    for (int t = tid; t < 96 * 15; t += 256) {
        int n = t / 15, c = t % 15;
        snat[t] = g_atoms[(size_t)(b * LL + eidx_s[n]) * 15 + c];
    }
    __syncthreads();   // <-- FIX (R4 bug): snat/ssat/dcls must be visible to
                       //     all warps before any feature-chunk compute reads

    // prologue: W chunks 0,1 into ring stages 0,1
#pragma unroll
    for (int q = 0; q < 2; q++) {
        unsigned bst = smW + (unsigned)(q & 3) * WWRD * 4;
#pragma unroll
        for (int e = 0; e < 4; e++) {
            int idx = tid + e * 256;            // 0..1023
            int r = idx >> 5, cgr = idx & 31;   // row 0..31, 16B-granule 0..31
            cp16(bst + (unsigned)(r * WSTR + cgr * 4) * 4,
                 g_Wt + (size_t)(q * 32 + r) * ED + cgr * 4);
        }
        cp_commit();
    }

    float acc[3][4][4];
#pragma unroll
    for (int rt = 0; rt < 3; rt++)
#pragma unroll
        for (int j = 0; j < 4; j++)
#pragma unroll
            for (int c = 0; c < 4; c++) acc[rt][j][c] = 0.0f;

    int rg = wid >> 2, cg = wid & 3;
    int rowbase = rg * 48;
    int colbase = cg * 32;

    for (int c = 0; c < NCH; c++) {
        // ---- compute feature chunk c into A stage (c&1) ----
        unsigned* Ab = dsm + (c & 1) * AWRD;
        if (c == 0) {
            if (tid < 96) {
                int row = tid, dc = dcls[row];
#pragma unroll
                for (int j = 0; j < 16; j++)
                    Ab[row * ASTR + j] = f2tf(Wpos[dc * 16 + j] + bposs[j]);
            } else if (tid < 192) {
                int row = tid - 96;                 // pair 0 (Ca-Ca)
                int nl = row / KNN;
                float dx = ssat[nl * 15 + 0] - snat[row * 15 + 0];
                float dy = ssat[nl * 15 + 1] - snat[row * 15 + 1];
                float dz = ssat[nl * 15 + 2] - snat[row * 15 + 2];
                float Dp = sqrtf(dx * dx + dy * dy + dz * dz + 1e-6f);
#pragma unroll
                for (int rr = 0; rr < 16; rr++) {
                    float mu = 2.0f + (20.0f / 15.0f) * (float)rr;
                    float z  = (Dp - mu) * 0.8f;
                    Ab[row * ASTR + 16 + rr] = f2tf(__expf(-z * z));
                }
            }
        } else if (tid < 192) {
            int pi = tid / 96, row = tid % 96;
            int nl = row / KNN;
            int p  = 2 * c - 1 + pi;               // pair 1..24
            int a1 = p / 5, a2 = p % 5;
            float dx = ssat[nl * 15 + a1 * 3 + 0] - snat[row * 15 + a2 * 3 + 0];
            float dy = ssat[nl * 15 + a1 * 3 + 1] - snat[row * 15 + a2 * 3 + 1];
            float dz = ssat[nl * 15 + a1 * 3 + 2] - snat[row * 15 + a2 * 3 + 2];
            float Dp = sqrtf(dx * dx + dy * dy + dz * dz + 1e-6f);
            int cb = 16 * pi;
#pragma unroll
            for (int rr = 0; rr < 16; rr++) {
                float mu = 2.0f + (20.0f / 15.0f) * (float)rr;
                float z  = (Dp - mu) * 0.8f;
                Ab[row * ASTR + cb + rr] = f2tf(__expf(-z * z));
            }
        }

        // ---- issue W chunk c+2 into ring stage (c+2)&3 ----
        if (c + 2 < NCH) {
            int q = c + 2;
            unsigned bst = smW + (unsigned)(q & 3) * WWRD * 4;
#pragma unroll
            for (int e = 0; e < 4; e++) {
                int idx = tid + e * 256;
                int r = idx >> 5, cgr = idx & 31;
                cp16(bst + (unsigned)(r * WSTR + cgr * 4) * 4,
                     g_Wt + (size_t)(q * 32 + r) * ED + cgr * 4);
            }
        }
        cp_commit();
        cp_wait2();              // W chunk c landed (this thread's copies)
        __syncthreads();         // A(c) + everyone's W(c) visible

        // ---- MMA on chunk c ----
        unsigned* Wb = dsm + 2 * AWRD + (c & 3) * WWRD;
#pragma unroll
        for (int s = 0; s < 4; s++) {
            int kb = s * 8;
            unsigned a[3][4];
#pragma unroll
            for (int rt = 0; rt < 3; rt++) {
                int r0 = rowbase + rt * 16 + gid;
                a[rt][0] = Ab[r0 * ASTR + kb + tg];
                a[rt][1] = Ab[(r0 + 8) * ASTR + kb + tg];
                a[rt][2] = Ab[r0 * ASTR + kb + tg + 4];
                a[rt][3] = Ab[(r0 + 8) * ASTR + kb + tg + 4];
            }
            unsigned bf[4][2];
#pragma unroll
            for (int j = 0; j < 4; j++) {
                bf[j][0] = Wb[(kb + tg) * WSTR + colbase + j * 8 + gid];
                bf[j][1] = Wb[(kb + tg + 4) * WSTR + colbase + j * 8 + gid];
            }
#pragma unroll
            for (int rt = 0; rt < 3; rt++)
#pragma unroll
                for (int j = 0; j < 4; j++)
                    MMA_TF32(acc[rt][j], a[rt], bf[j]);
        }
    }

    // ---- epilogue: stage C (reuse W ring region), LN, store ----
    __syncthreads();
    float* stage = (float*)(dsm + 2 * AWRD);   // 96*132 floats fits in W ring
#pragma unroll
    for (int rt = 0; rt < 3; rt++)
#pragma unroll
        for (int j = 0; j < 4; j++) {
            int row = rowbase + rt * 16 + gid;
            int col = colbase + j * 8 + 2 * tg;
            *(float2*)&stage[row * WSTR + col] =
                make_float2(acc[rt][j][0], acc[rt][j][1]);
            *(float2*)&stage[(row + 8) * WSTR + col] =
                make_float2(acc[rt][j][2], acc[rt][j][3]);
        }
    __syncthreads();

    size_t obase = (size_t)node0 * KNN * ED;
    int tx = tid & 15, ty = tid >> 4;
#pragma unroll
    for (int rr = 0; rr < 6; rr++) {
        int row = ty + 16 * rr;
        float v8[8];
#pragma unroll
        for (int cc = 0; cc < 4; cc++)
            *(float2*)&v8[cc * 2] = *(float2*)&stage[row * WSTR + tx * 8 + cc * 2];
        float s = 0.0f;
#pragma unroll
        for (int cc = 0; cc < 8; cc++) s += v8[cc];
#pragma unroll
        for (int off = 8; off > 0; off >>= 1)
            s += __shfl_xor_sync(0xffffffffu, s, off);
        float mean = s * (1.0f / 128.0f);
        float var = 0.0f;
#pragma unroll
        for (int cc = 0; cc < 8; cc++) { float d = v8[cc] - mean; var += d * d; }
#pragma unroll
        for (int off = 8; off > 0; off >>= 1)
            var += __shfl_xor_sync(0xffffffffu, var, off);
        float rs = rsqrtf(var * (1.0f / 128.0f) + 1e-5f);
        float out[8];
#pragma unroll
        for (int cc = 0; cc < 8; cc++)
            out[cc] = (v8[cc] - mean) * rs * gam[tx * 8 + cc] + bet[tx * 8 + cc];
        float* dst = outE + obase + (size_t)row * ED + tx * 8;
        *(float4*)dst       = make_float4(out[0], out[1], out[2], out[3]);
        *(float4*)(dst + 4) = make_float4(out[4], out[5], out[6], out[7]);
    }
}

// ---------------------------------------------------------------------------
extern "C" void kernel_launch(void* const* d_in, const int* in_sizes, int n_in,
                              void* d_out, int out_size) {
    const float* X     = (const float*)d_in[0];
    const float* mask  = (const float*)d_in[1];
    const int*   ridx  = (const int*)d_in[2];
    const int*   chain = (const int*)d_in[3];
    const float* Wpos  = (const float*)d_in[4];
    const float* bpos  = (const float*)d_in[5];
    const float* Wedge = (const float*)d_in[6];
    const float* gam   = (const float*)d_in[7];
    const float* bet   = (const float*)d_in[8];

    float* outE = (float*)d_out;
    size_t nE = (size_t)BB * LL * KNN * ED;
    float* outI = ((size_t)out_size > nE) ? (outE + nE) : nullptr;

    wt_kernel<<<(416 * ED + 255) / 256, 256>>>(Wedge);
    atoms_kernel<<<(BB * LL + 255) / 256, 256>>>(X);
    topk_kernel<<<BB * LL, 256>>>(X, mask, outI);

    static const int smemK3 = (2 * AWRD + 4 * WWRD) * 4;   // 95232 B
    cudaFuncSetAttribute(edge_kernel,
                         cudaFuncAttributeMaxDynamicSharedMemorySize, smemK3);
    edge_kernel<<<BB * LL / 2, 256, smemK3>>>(ridx, chain, Wpos, bpos,
                                              gam, bet, outE);
    (void)in_sizes; (void)n_in;
}

// round 6
// speedup vs baseline: 3.9297x; 1.3276x over previous
#include <cuda_runtime.h>
#include <cstdint>

#define BB   2
#define LL   2048
#define KNN  48
#define ED   128
#define NCH  13            // 13 K-chunks of 32 fp32 cols = K=416

#define ASTR 36            // A smem row stride (u32 words) -> conflict-free frags
#define WSTR 132           // W smem row stride (u32 words) -> conflict-free frags
#define AWRD (96 * ASTR)   // words per A stage = 3456
#define WWRD (32 * WSTR)   // words per W stage = 4224

// scratch (allocation-free rule: __device__ globals)
__device__ float    g_atoms[BB * LL * 15];
__device__ int      g_eidx[BB * LL * KNN];
__device__ unsigned g_Wt[416 * ED];   // W tf32-rounded bits, layout [k][n]

__device__ __forceinline__ unsigned f2tf(float x) {
    unsigned r;
    asm("cvt.rna.tf32.f32 %0, %1;" : "=r"(r) : "f"(x));
    return r;
}
__device__ __forceinline__ unsigned smem_u32(const void* p) {
    unsigned a;
    asm("{ .reg .u64 t; cvta.to.shared.u64 t, %1; cvt.u32.u64 %0, t; }"
        : "=r"(a) : "l"(p));
    return a;
}
__device__ __forceinline__ void cp16(unsigned dst, const void* src) {
    asm volatile("cp.async.cg.shared.global [%0], [%1], 16;" :: "r"(dst), "l"(src));
}
__device__ __forceinline__ void cp_commit() {
    asm volatile("cp.async.commit_group;" ::: "memory");
}
__device__ __forceinline__ void cp_wait2() {
    asm volatile("cp.async.wait_group 2;" ::: "memory");
}

#define MMA_TF32(d, a, b)                                                     \
    asm volatile(                                                             \
        "mma.sync.aligned.m16n8k8.row.col.f32.tf32.tf32.f32 "                 \
        "{%0,%1,%2,%3}, {%4,%5,%6,%7}, {%8,%9}, {%0,%1,%2,%3};"               \
        : "+f"(d[0]), "+f"(d[1]), "+f"(d[2]), "+f"(d[3])                      \
        : "r"(a[0]), "r"(a[1]), "r"(a[2]), "r"(a[3]), "r"(b[0]), "r"(b[1]))

// ---------------------------------------------------------------------------
// Kernel 0: pre-round W to tf32 bits (same [k][n] layout)
// ---------------------------------------------------------------------------
__global__ void wt_kernel(const float* __restrict__ W) {
    int idx = blockIdx.x * blockDim.x + threadIdx.x;
    if (idx < 416 * ED) g_Wt[idx] = f2tf(W[idx]);
}

// ---------------------------------------------------------------------------
// Kernel 1: build atoms[Ca,N,C,O,Cb] per residue
// ---------------------------------------------------------------------------
__global__ void atoms_kernel(const float* __restrict__ X) {
    int idx = blockIdx.x * blockDim.x + threadIdx.x;
    if (idx >= BB * LL) return;
    const float* x = X + (size_t)idx * 12;
    float Nx = x[0],  Ny = x[1],  Nz = x[2];
    float Cax = x[3], Cay = x[4], Caz = x[5];
    float Cx = x[6],  Cy = x[7],  Cz = x[8];
    float Ox = x[9],  Oy = x[10], Oz = x[11];

    float bx = Cax - Nx,  by = Cay - Ny,  bz = Caz - Nz;
    float cx = Cx - Cax,  cy = Cy - Cay,  cz = Cz - Caz;
    float ax = by * cz - bz * cy;
    float ay = bz * cx - bx * cz;
    float az = bx * cy - by * cx;
    float Cbx = -0.58273431f * ax + 0.56802827f * bx - 0.54067466f * cx + Cax;
    float Cby = -0.58273431f * ay + 0.56802827f * by - 0.54067466f * cy + Cay;
    float Cbz = -0.58273431f * az + 0.56802827f * bz - 0.54067466f * cz + Caz;

    float* o = g_atoms + (size_t)idx * 15;
    o[0]  = Cax; o[1]  = Cay; o[2]  = Caz;
    o[3]  = Nx;  o[4]  = Ny;  o[5]  = Nz;
    o[6]  = Cx;  o[7]  = Cy;  o[8]  = Cz;
    o[9]  = Ox;  o[10] = Oy;  o[11] = Oz;
    o[12] = Cbx; o[13] = Cby; o[14] = Cbz;
}

// ---------------------------------------------------------------------------
// Radix-select helper: warp 0 scans hist[256], finds pivot bin where the
// cumulative count crosses thr. Sets *s_pivot (bin) and *s_base (count
// strictly below pivot bin). Exactly one lane/j satisfies the cross.
// ---------------------------------------------------------------------------
__device__ __forceinline__ void scan_pivot(const unsigned* hist, unsigned thr,
                                           unsigned* s_pivot, unsigned* s_base,
                                           int tid) {
    if (tid < 32) {
        unsigned v[8], pre[8], s = 0;
#pragma unroll
        for (int j = 0; j < 8; j++) { v[j] = hist[tid * 8 + j]; pre[j] = s; s += v[j]; }
        unsigned tot = s, x = tot;
#pragma unroll
        for (int off = 1; off < 32; off <<= 1) {
            unsigned y = __shfl_up_sync(0xffffffffu, x, off);
            if (tid >= off) x += y;
        }
        unsigned ex = x - tot;   // exclusive prefix across lanes
        if (ex < thr && ex + tot >= thr) {
#pragma unroll
            for (int j = 0; j < 8; j++) {
                unsigned cb = ex + pre[j];
                if (cb < thr && cb + v[j] >= thr) { *s_pivot = tid * 8 + j; *s_base = cb; }
            }
        }
    }
}

// ---------------------------------------------------------------------------
// Kernel 2: top-K via exact 2-level radix select + tiny extraction + bitonic
// sort of the 48 winners. Keys = (f32bits(adjdist) << 32) | index — identical
// ordering to jax.lax.top_k(-D) with lower-index tie-break.
// ---------------------------------------------------------------------------
__global__ void __launch_bounds__(256) topk_kernel(const float* __restrict__ X,
                                                   const float* __restrict__ mask,
                                                   float* __restrict__ outI) {
    __shared__ __align__(16) char sbuf[32768];
    float* cxs = (float*)sbuf;
    float* cys = cxs + LL;
    float* czs = cys + LL;
    float* mms = czs + LL;
    unsigned long long* cand1 = (unsigned long long*)sbuf;            // 16KB
    unsigned long long* cand2 = (unsigned long long*)(sbuf + 16384);  // 16KB
    __shared__ unsigned hist[256];
    __shared__ unsigned long long win[64];
    __shared__ unsigned s_nwin, s_nc1, s_nc2, s_pivot, s_base;
    __shared__ float wmaxs[8];
    __shared__ float s_dmax;

    int b   = blockIdx.x >> 11;
    int i   = blockIdx.x & (LL - 1);
    int tid = threadIdx.x;
    int lane = tid & 31, wid = tid >> 5;

    for (int t = tid; t < LL; t += 256) {
        const float* p = X + ((size_t)(b * LL + t) * 4 + 1) * 3;   // Ca
        cxs[t] = p[0]; cys[t] = p[1]; czs[t] = p[2];
        mms[t] = mask[b * LL + t];
    }
    __syncthreads();

    float xi = cxs[i], yi = cys[i], zi = czs[i], mi = mms[i];
    float dv[8], m2v[8];
    float dmax = 0.0f;
#pragma unroll
    for (int u = 0; u < 8; u++) {
        int j = tid * 8 + u;
        // exact fp32 op order, no fma-contraction, IEEE sqrt (matches XLA)
        float dx = __fsub_rn(cxs[j], xi);
        float dy = __fsub_rn(cys[j], yi);
        float dz = __fsub_rn(czs[j], zi);
        float s  = __fadd_rn(__fadd_rn(__fmul_rn(dx, dx), __fmul_rn(dy, dy)),
                             __fmul_rn(dz, dz));
        float dd  = __fsqrt_rn(__fadd_rn(s, 1e-6f));
        float mij = __fmul_rn(mi, mms[j]);
        dv[u]  = __fmul_rn(mij, dd);
        m2v[u] = mij;
        dmax = fmaxf(dmax, dv[u]);
    }
#pragma unroll
    for (int off = 16; off > 0; off >>= 1)
        dmax = fmaxf(dmax, __shfl_xor_sync(0xffffffffu, dmax, off));
    if (lane == 0) wmaxs[wid] = dmax;
    __syncthreads();
    if (tid == 0) {
        float m = wmaxs[0];
        for (int w = 1; w < 8; w++) m = fmaxf(m, wmaxs[w]);
        s_dmax = m;
    }
    __syncthreads();
    float dmx = s_dmax;

    unsigned long long k[8];
#pragma unroll
    for (int u = 0; u < 8; u++) {
        float adj = __fadd_rn(dv[u], __fmul_rn(__fsub_rn(1.0f, m2v[u]), dmx));
        k[u] = ((unsigned long long)__float_as_uint(adj) << 32) |
               (unsigned)(tid * 8 + u);
    }
    __syncthreads();   // done reading coordinate smem; safe to alias as cand*

    // ---- level 1: histogram on key bits [63:56] ----
    hist[tid] = 0;
    if (tid == 0) { s_nwin = 0; s_nc1 = 0; s_nc2 = 0; }
    __syncthreads();
#pragma unroll
    for (int u = 0; u < 8; u++)
        atomicAdd(&hist[(unsigned)(k[u] >> 56)], 1u);
    __syncthreads();
    scan_pivot(hist, 48u, &s_pivot, &s_base, tid);
    __syncthreads();
    unsigned p1 = s_pivot, base1 = s_base;
#pragma unroll
    for (int u = 0; u < 8; u++) {
        unsigned bn = (unsigned)(k[u] >> 56);
        if (bn < p1)       win[atomicAdd(&s_nwin, 1u)]   = k[u];
        else if (bn == p1) cand1[atomicAdd(&s_nc1, 1u)]  = k[u];
    }
    __syncthreads();

    // ---- level 2: histogram on key bits [55:48] within pivot bin ----
    unsigned need = 48u - base1;   // >= 1 by construction
    hist[tid] = 0;
    __syncthreads();
    unsigned nc1 = s_nc1;
    for (unsigned t = tid; t < nc1; t += 256)
        atomicAdd(&hist[(unsigned)(cand1[t] >> 48) & 255u], 1u);
    __syncthreads();
    scan_pivot(hist, need, &s_pivot, &s_base, tid);
    __syncthreads();
    unsigned p2 = s_pivot;
    for (unsigned t = tid; t < nc1; t += 256) {
        unsigned long long v = cand1[t];
        unsigned bn = (unsigned)(v >> 48) & 255u;
        if (bn < p2)       win[atomicAdd(&s_nwin, 1u)]  = v;
        else if (bn == p2) cand2[atomicAdd(&s_nc2, 1u)] = v;
    }
    __syncthreads();

    // ---- exact extraction of the remaining winners from cand2 ----
    if (wid == 0) {
        int m2 = (int)s_nc2;
        int nw = (int)s_nwin;
        int rem = 48 - nw;        // >= 1
        for (int r = 0; r < rem; r++) {
            unsigned long long best = ~0ull; int bp = -1;
            for (int t = lane; t < m2; t += 32) {
                unsigned long long v = cand2[t];
                if (v < best) { best = v; bp = t; }
            }
#pragma unroll
            for (int off = 16; off > 0; off >>= 1) {
                unsigned long long o = __shfl_xor_sync(0xffffffffu, best, off);
                int op = __shfl_xor_sync(0xffffffffu, bp, off);
                if (o < best) { best = o; bp = op; }
            }
            if (lane == 0) { win[nw + r] = best; cand2[bp] = ~0ull; }
            __syncwarp();
        }
    }
    if (tid >= 48 && tid < 64) win[tid] = ~0ull;
    __syncthreads();

    // ---- exact bitonic sort of 64 slots (48 keys + INF pads), warp 0 ----
    if (wid == 0) {
        unsigned long long a0 = win[2 * lane], a1 = win[2 * lane + 1];
#pragma unroll
        for (int kk = 2; kk <= 64; kk <<= 1) {
#pragma unroll
            for (int j = kk >> 1; j >= 1; j >>= 1) {
                bool up = ((2 * lane) & kk) == 0;
                if (j == 1) {
                    if (up ? (a0 > a1) : (a0 < a1)) {
                        unsigned long long t = a0; a0 = a1; a1 = t;
                    }
                } else {
                    int d = j >> 1;
                    bool lower = (lane & d) == 0;
                    unsigned long long q0 = __shfl_xor_sync(0xffffffffu, a0, d);
                    unsigned long long q1 = __shfl_xor_sync(0xffffffffu, a1, d);
                    bool keepmin = (up == lower);
                    a0 = keepmin ? (a0 < q0 ? a0 : q0) : (a0 > q0 ? a0 : q0);
                    a1 = keepmin ? (a1 < q1 ? a1 : q1) : (a1 > q1 ? a1 : q1);
                }
            }
        }
        size_t baseo = (size_t)(b * LL + i) * KNN;
        int r0 = 2 * lane, r1 = 2 * lane + 1;
        if (r0 < KNN) {
            int j = (int)(unsigned)(a0 & 0xffffffffull);
            g_eidx[baseo + r0] = j;
            if (outI) outI[baseo + r0] = (float)j;
        }
        if (r1 < KNN) {
            int j = (int)(unsigned)(a1 & 0xffffffffull);
            g_eidx[baseo + r1] = j;
            if (outI) outI[baseo + r1] = (float)j;
        }
    }
}

// ---------------------------------------------------------------------------
// Kernel 3 (hot): 2 nodes per CTA (96x128 tile). Feature chunks (double-buf)
// + pre-tf32 W via 4-stage cp.async ring + mma.sync tf32 + fused LayerNorm.
// 8 warps: warp = 48 rows x 32 cols (rg = wid>>2, cg = wid&3).
// dynamic smem: A[2][96*36]u32 + W[4][32*132]u32 = 95232 B.
// ---------------------------------------------------------------------------
__global__ void __launch_bounds__(256, 2) edge_kernel(
    const int* __restrict__ ridx, const int* __restrict__ chain,
    const float* __restrict__ Wpos, const float* __restrict__ bpos,
    const float* __restrict__ gamma_, const float* __restrict__ beta_,
    float* __restrict__ outE) {
    extern __shared__ unsigned dsm[];
    __shared__ float ssat[2 * 15];
    __shared__ float snat[96 * 15];
    __shared__ float gam[ED], bet[ED];
    __shared__ float bposs[16];
    __shared__ int   eidx_s[96];
    __shared__ int   dcls[96];

    int tid  = threadIdx.x;
    int wid  = tid >> 5;
    int lane = tid & 31;
    int gid  = lane >> 2, tg = lane & 3;
    int node0 = 2 * blockIdx.x;
    int b = node0 >> 11;

    unsigned smW = smem_u32(dsm) + 2 * AWRD * 4;

    if (tid < ED) { gam[tid] = gamma_[tid]; bet[tid] = beta_[tid]; }
    if (tid < 16) bposs[tid] = bpos[tid];
    if (tid < 96) eidx_s[tid] = g_eidx[(size_t)node0 * KNN + tid];
    if (tid >= 128 && tid < 158) ssat[tid - 128] = g_atoms[(size_t)node0 * 15 + (tid - 128)];
    __syncthreads();

    if (tid < 96) {
        int nl = tid / KNN;
        int j  = eidx_s[tid];
        int ng = node0 + nl;
        int off  = ridx[ng] - ridx[b * LL + j];
        int same = (chain[ng] == chain[b * LL + j]);
        int d = off + 32;
        d = d < 0 ? 0 : (d > 64 ? 64 : d);
        dcls[tid] = same ? d : 65;
    }
    for (int t = tid; t < 96 * 15; t += 256) {
        int n = t / 15, c = t % 15;
        snat[t] = g_atoms[(size_t)(b * LL + eidx_s[n]) * 15 + c];
    }
    __syncthreads();   // snat/ssat/dcls visible before feature compute

    // prologue: W chunks 0,1 into ring stages 0,1
#pragma unroll
    for (int q = 0; q < 2; q++) {
        unsigned bst = smW + (unsigned)(q & 3) * WWRD * 4;
#pragma unroll
        for (int e = 0; e < 4; e++) {
            int idx = tid + e * 256;            // 0..1023
            int r = idx >> 5, cgr = idx & 31;   // row 0..31, 16B-granule 0..31
            cp16(bst + (unsigned)(r * WSTR + cgr * 4) * 4,
                 g_Wt + (size_t)(q * 32 + r) * ED + cgr * 4);
        }
        cp_commit();
    }

    float acc[3][4][4];
#pragma unroll
    for (int rt = 0; rt < 3; rt++)
#pragma unroll
        for (int j = 0; j < 4; j++)
#pragma unroll
            for (int c = 0; c < 4; c++) acc[rt][j][c] = 0.0f;

    int rg = wid >> 2, cg = wid & 3;
    int rowbase = rg * 48;
    int colbase = cg * 32;

    for (int c = 0; c < NCH; c++) {
        // ---- compute feature chunk c into A stage (c&1) ----
        unsigned* Ab = dsm + (c & 1) * AWRD;
        if (c == 0) {
            if (tid < 96) {
                int row = tid, dc = dcls[row];
#pragma unroll
                for (int j = 0; j < 16; j++)
                    Ab[row * ASTR + j] = f2tf(Wpos[dc * 16 + j] + bposs[j]);
            } else if (tid < 192) {
                int row = tid - 96;                 // pair 0 (Ca-Ca)
                int nl = row / KNN;
                float dx = ssat[nl * 15 + 0] - snat[row * 15 + 0];
                float dy = ssat[nl * 15 + 1] - snat[row * 15 + 1];
                float dz = ssat[nl * 15 + 2] - snat[row * 15 + 2];
                float Dp = sqrtf(dx * dx + dy * dy + dz * dz + 1e-6f);
#pragma unroll
                for (int rr = 0; rr < 16; rr++) {
                    float mu = 2.0f + (20.0f / 15.0f) * (float)rr;
                    float z  = (Dp - mu) * 0.8f;
                    Ab[row * ASTR + 16 + rr] = f2tf(__expf(-z * z));
                }
            }
        } else if (tid < 192) {
            int pi = tid / 96, row = tid % 96;
            int nl = row / KNN;
            int p  = 2 * c - 1 + pi;               // pair 1..24
            int a1 = p / 5, a2 = p % 5;
            float dx = ssat[nl * 15 + a1 * 3 + 0] - snat[row * 15 + a2 * 3 + 0];
            float dy = ssat[nl * 15 + a1 * 3 + 1] - snat[row * 15 + a2 * 3 + 1];
            float dz = ssat[nl * 15 + a1 * 3 + 2] - snat[row * 15 + a2 * 3 + 2];
            float Dp = sqrtf(dx * dx + dy * dy + dz * dz + 1e-6f);
            int cb = 16 * pi;
#pragma unroll
            for (int rr = 0; rr < 16; rr++) {
                float mu = 2.0f + (20.0f / 15.0f) * (float)rr;
                float z  = (Dp - mu) * 0.8f;
                Ab[row * ASTR + cb + rr] = f2tf(__expf(-z * z));
            }
        }

        // ---- issue W chunk c+2 into ring stage (c+2)&3 ----
        if (c + 2 < NCH) {
            int q = c + 2;
            unsigned bst = smW + (unsigned)(q & 3) * WWRD * 4;
#pragma unroll
            for (int e = 0; e < 4; e++) {
                int idx = tid + e * 256;
                int r = idx >> 5, cgr = idx & 31;
                cp16(bst + (unsigned)(r * WSTR + cgr * 4) * 4,
                     g_Wt + (size_t)(q * 32 + r) * ED + cgr * 4);
            }
        }
        cp_commit();
        cp_wait2();              // W chunk c landed (this thread's copies)
        __syncthreads();         // A(c) + everyone's W(c) visible

        // ---- MMA on chunk c ----
        unsigned* Wb = dsm + 2 * AWRD + (c & 3) * WWRD;
#pragma unroll
        for (int s = 0; s < 4; s++) {
            int kb = s * 8;
            unsigned a[3][4];
#pragma unroll
            for (int rt = 0; rt < 3; rt++) {
                int r0 = rowbase + rt * 16 + gid;
                a[rt][0] = Ab[r0 * ASTR + kb + tg];
                a[rt][1] = Ab[(r0 + 8) * ASTR + kb + tg];
                a[rt][2] = Ab[r0 * ASTR + kb + tg + 4];
                a[rt][3] = Ab[(r0 + 8) * ASTR + kb + tg + 4];
            }
            unsigned bf[4][2];
#pragma unroll
            for (int j = 0; j < 4; j++) {
                bf[j][0] = Wb[(kb + tg) * WSTR + colbase + j * 8 + gid];
                bf[j][1] = Wb[(kb + tg + 4) * WSTR + colbase + j * 8 + gid];
            }
#pragma unroll
            for (int rt = 0; rt < 3; rt++)
#pragma unroll
                for (int j = 0; j < 4; j++)
                    MMA_TF32(acc[rt][j], a[rt], bf[j]);
        }
    }

    // ---- epilogue: stage C (reuse W ring region), LN, store ----
    __syncthreads();
    float* stage = (float*)(dsm + 2 * AWRD);   // 96*132 floats fits in W ring
#pragma unroll
    for (int rt = 0; rt < 3; rt++)
#pragma unroll
        for (int j = 0; j < 4; j++) {
            int row = rowbase + rt * 16 + gid;
            int col = colbase + j * 8 + 2 * tg;
            *(float2*)&stage[row * WSTR + col] =
                make_float2(acc[rt][j][0], acc[rt][j][1]);
            *(float2*)&stage[(row + 8) * WSTR + col] =
                make_float2(acc[rt][j][2], acc[rt][j][3]);
        }
    __syncthreads();

    size_t obase = (size_t)node0 * KNN * ED;
    int tx = tid & 15, ty = tid >> 4;
#pragma unroll
    for (int rr = 0; rr < 6; rr++) {
        int row = ty + 16 * rr;
        float v8[8];
#pragma unroll
        for (int cc = 0; cc < 4; cc++)
            *(float2*)&v8[cc * 2] = *(float2*)&stage[row * WSTR + tx * 8 + cc * 2];
        float s = 0.0f;
#pragma unroll
        for (int cc = 0; cc < 8; cc++) s += v8[cc];
#pragma unroll
        for (int off = 8; off > 0; off >>= 1)
            s += __shfl_xor_sync(0xffffffffu, s, off);
        float mean = s * (1.0f / 128.0f);
        float var = 0.0f;
#pragma unroll
        for (int cc = 0; cc < 8; cc++) { float d = v8[cc] - mean; var += d * d; }
#pragma unroll
        for (int off = 8; off > 0; off >>= 1)
            var += __shfl_xor_sync(0xffffffffu, var, off);
        float rs = rsqrtf(var * (1.0f / 128.0f) + 1e-5f);
        float out[8];
#pragma unroll
        for (int cc = 0; cc < 8; cc++)
            out[cc] = (v8[cc] - mean) * rs * gam[tx * 8 + cc] + bet[tx * 8 + cc];
        float* dst = outE + obase + (size_t)row * ED + tx * 8;
        *(float4*)dst       = make_float4(out[0], out[1], out[2], out[3]);
        *(float4*)(dst + 4) = make_float4(out[4], out[5], out[6], out[7]);
    }
}

// ---------------------------------------------------------------------------
extern "C" void kernel_launch(void* const* d_in, const int* in_sizes, int n_in,
                              void* d_out, int out_size) {
    const float* X     = (const float*)d_in[0];
    const float* mask  = (const float*)d_in[1];
    const int*   ridx  = (const int*)d_in[2];
    const int*   chain = (const int*)d_in[3];
    const float* Wpos  = (const float*)d_in[4];
    const float* bpos  = (const float*)d_in[5];
    const float* Wedge = (const float*)d_in[6];
    const float* gam   = (const float*)d_in[7];
    const float* bet   = (const float*)d_in[8];

    float* outE = (float*)d_out;
    size_t nE = (size_t)BB * LL * KNN * ED;
    float* outI = ((size_t)out_size > nE) ? (outE + nE) : nullptr;

    wt_kernel<<<(416 * ED + 255) / 256, 256>>>(Wedge);
    atoms_kernel<<<(BB * LL + 255) / 256, 256>>>(X);
    topk_kernel<<<BB * LL, 256>>>(X, mask, outI);

    static const int smemK3 = (2 * AWRD + 4 * WWRD) * 4;   // 95232 B
    cudaFuncSetAttribute(edge_kernel,
                         cudaFuncAttributeMaxDynamicSharedMemorySize, smemK3);
    edge_kernel<<<BB * LL / 2, 256, smemK3>>>(ridx, chain, Wpos, bpos,
                                              gam, bet, outE);
    (void)in_sizes; (void)n_in;
}

// round 7
// speedup vs baseline: 3.9594x; 1.0076x over previous
#include <cuda_runtime.h>
#include <cstdint>

#define BB   2
#define LL   2048
#define KNN  48
#define ED   128
#define NCH  13            // 13 K-chunks of 32 fp32 cols = K=416

#define ASTR 36            // A smem row stride (u32 words) -> conflict-free frags
#define WSTR 132           // W smem row stride (u32 words) -> conflict-free frags
#define AWRD (96 * ASTR)   // words per A stage = 3456
#define WWRD (32 * WSTR)   // words per W stage = 4224

// scratch (allocation-free rule: __device__ globals)
__device__ float    g_atoms[BB * LL * 15];
__device__ int      g_eidx[BB * LL * KNN];
__device__ unsigned g_Wt[416 * ED];   // W tf32-rounded bits, layout [k][n]

__device__ __forceinline__ unsigned f2tf(float x) {
    unsigned r;
    asm("cvt.rna.tf32.f32 %0, %1;" : "=r"(r) : "f"(x));
    return r;
}
__device__ __forceinline__ unsigned smem_u32(const void* p) {
    unsigned a;
    asm("{ .reg .u64 t; cvta.to.shared.u64 t, %1; cvt.u32.u64 %0, t; }"
        : "=r"(a) : "l"(p));
    return a;
}
__device__ __forceinline__ void cp16(unsigned dst, const void* src) {
    asm volatile("cp.async.cg.shared.global [%0], [%1], 16;" :: "r"(dst), "l"(src));
}
__device__ __forceinline__ void cp_commit() {
    asm volatile("cp.async.commit_group;" ::: "memory");
}
__device__ __forceinline__ void cp_wait2() {
    asm volatile("cp.async.wait_group 2;" ::: "memory");
}

#define MMA_TF32(d, a, b)                                                     \
    asm volatile(                                                             \
        "mma.sync.aligned.m16n8k8.row.col.f32.tf32.tf32.f32 "                 \
        "{%0,%1,%2,%3}, {%4,%5,%6,%7}, {%8,%9}, {%0,%1,%2,%3};"               \
        : "+f"(d[0]), "+f"(d[1]), "+f"(d[2]), "+f"(d[3])                      \
        : "r"(a[0]), "r"(a[1]), "r"(a[2]), "r"(a[3]), "r"(b[0]), "r"(b[1]))

// ---------------------------------------------------------------------------
// Kernel 0: pre-round W to tf32 bits (same [k][n] layout)
// ---------------------------------------------------------------------------
__global__ void wt_kernel(const float* __restrict__ W) {
    int idx = blockIdx.x * blockDim.x + threadIdx.x;
    if (idx < 416 * ED) g_Wt[idx] = f2tf(W[idx]);
}

// ---------------------------------------------------------------------------
// Kernel 1: build atoms[Ca,N,C,O,Cb] per residue
// ---------------------------------------------------------------------------
__global__ void atoms_kernel(const float* __restrict__ X) {
    int idx = blockIdx.x * blockDim.x + threadIdx.x;
    if (idx >= BB * LL) return;
    const float* x = X + (size_t)idx * 12;
    float Nx = x[0],  Ny = x[1],  Nz = x[2];
    float Cax = x[3], Cay = x[4], Caz = x[5];
    float Cx = x[6],  Cy = x[7],  Cz = x[8];
    float Ox = x[9],  Oy = x[10], Oz = x[11];

    float bx = Cax - Nx,  by = Cay - Ny,  bz = Caz - Nz;
    float cx = Cx - Cax,  cy = Cy - Cay,  cz = Cz - Caz;
    float ax = by * cz - bz * cy;
    float ay = bz * cx - bx * cz;
    float az = bx * cy - by * cx;
    float Cbx = -0.58273431f * ax + 0.56802827f * bx - 0.54067466f * cx + Cax;
    float Cby = -0.58273431f * ay + 0.56802827f * by - 0.54067466f * cy + Cay;
    float Cbz = -0.58273431f * az + 0.56802827f * bz - 0.54067466f * cz + Caz;

    float* o = g_atoms + (size_t)idx * 15;
    o[0]  = Cax; o[1]  = Cay; o[2]  = Caz;
    o[3]  = Nx;  o[4]  = Ny;  o[5]  = Nz;
    o[6]  = Cx;  o[7]  = Cy;  o[8]  = Cz;
    o[9]  = Ox;  o[10] = Oy;  o[11] = Oz;
    o[12] = Cbx; o[13] = Cby; o[14] = Cbz;
}

// ---------------------------------------------------------------------------
// Radix-select helper: warp 0 scans hist[256], finds pivot bin where the
// cumulative count crosses thr. Sets *s_pivot (bin) and *s_base (count
// strictly below pivot bin). Exactly one lane/j satisfies the cross.
// ---------------------------------------------------------------------------
__device__ __forceinline__ void scan_pivot(const unsigned* hist, unsigned thr,
                                           unsigned* s_pivot, unsigned* s_base,
                                           int tid) {
    if (tid < 32) {
        unsigned v[8], pre[8], s = 0;
#pragma unroll
        for (int j = 0; j < 8; j++) { v[j] = hist[tid * 8 + j]; pre[j] = s; s += v[j]; }
        unsigned tot = s, x = tot;
#pragma unroll
        for (int off = 1; off < 32; off <<= 1) {
            unsigned y = __shfl_up_sync(0xffffffffu, x, off);
            if (tid >= off) x += y;
        }
        unsigned ex = x - tot;   // exclusive prefix across lanes
        if (ex < thr && ex + tot >= thr) {
#pragma unroll
            for (int j = 0; j < 8; j++) {
                unsigned cb = ex + pre[j];
                if (cb < thr && cb + v[j] >= thr) { *s_pivot = tid * 8 + j; *s_base = cb; }
            }
        }
    }
}

// ---------------------------------------------------------------------------
// Kernel 2: top-K via exact 2-level radix select + tiny extraction + bitonic
// sort of the 48 winners. Keys = (f32bits(adjdist) << 32) | index — identical
// ordering to jax.lax.top_k(-D) with lower-index tie-break.
// ---------------------------------------------------------------------------
__global__ void __launch_bounds__(256) topk_kernel(const float* __restrict__ X,
                                                   const float* __restrict__ mask,
                                                   float* __restrict__ outI) {
    __shared__ __align__(16) char sbuf[32768];
    float* cxs = (float*)sbuf;
    float* cys = cxs + LL;
    float* czs = cys + LL;
    float* mms = czs + LL;
    unsigned long long* cand1 = (unsigned long long*)sbuf;            // 16KB
    unsigned long long* cand2 = (unsigned long long*)(sbuf + 16384);  // 16KB
    __shared__ unsigned hist[256];
    __shared__ unsigned long long win[64];
    __shared__ unsigned s_nwin, s_nc1, s_nc2, s_pivot, s_base;
    __shared__ float wmaxs[8];
    __shared__ float s_dmax;

    int b   = blockIdx.x >> 11;
    int i   = blockIdx.x & (LL - 1);
    int tid = threadIdx.x;
    int lane = tid & 31, wid = tid >> 5;

    for (int t = tid; t < LL; t += 256) {
        const float* p = X + ((size_t)(b * LL + t) * 4 + 1) * 3;   // Ca
        cxs[t] = p[0]; cys[t] = p[1]; czs[t] = p[2];
        mms[t] = mask[b * LL + t];
    }
    __syncthreads();

    float xi = cxs[i], yi = cys[i], zi = czs[i], mi = mms[i];
    float dv[8], m2v[8];
    float dmax = 0.0f;
#pragma unroll
    for (int u = 0; u < 8; u++) {
        int j = tid * 8 + u;
        // exact fp32 op order, no fma-contraction, IEEE sqrt (matches XLA)
        float dx = __fsub_rn(cxs[j], xi);
        float dy = __fsub_rn(cys[j], yi);
        float dz = __fsub_rn(czs[j], zi);
        float s  = __fadd_rn(__fadd_rn(__fmul_rn(dx, dx), __fmul_rn(dy, dy)),
                             __fmul_rn(dz, dz));
        float dd  = __fsqrt_rn(__fadd_rn(s, 1e-6f));
        float mij = __fmul_rn(mi, mms[j]);
        dv[u]  = __fmul_rn(mij, dd);
        m2v[u] = mij;
        dmax = fmaxf(dmax, dv[u]);
    }
#pragma unroll
    for (int off = 16; off > 0; off >>= 1)
        dmax = fmaxf(dmax, __shfl_xor_sync(0xffffffffu, dmax, off));
    if (lane == 0) wmaxs[wid] = dmax;
    __syncthreads();
    if (tid == 0) {
        float m = wmaxs[0];
        for (int w = 1; w < 8; w++) m = fmaxf(m, wmaxs[w]);
        s_dmax = m;
    }
    __syncthreads();
    float dmx = s_dmax;

    unsigned long long k[8];
#pragma unroll
    for (int u = 0; u < 8; u++) {
        float adj = __fadd_rn(dv[u], __fmul_rn(__fsub_rn(1.0f, m2v[u]), dmx));
        k[u] = ((unsigned long long)__float_as_uint(adj) << 32) |
               (unsigned)(tid * 8 + u);
    }
    __syncthreads();   // done reading coordinate smem; safe to alias as cand*

    // ---- level 1: histogram on key bits [63:56] ----
    hist[tid] = 0;
    if (tid == 0) { s_nwin = 0; s_nc1 = 0; s_nc2 = 0; }
    __syncthreads();
#pragma unroll
    for (int u = 0; u < 8; u++)
        atomicAdd(&hist[(unsigned)(k[u] >> 56)], 1u);
    __syncthreads();
    scan_pivot(hist, 48u, &s_pivot, &s_base, tid);
    __syncthreads();
    unsigned p1 = s_pivot, base1 = s_base;
#pragma unroll
    for (int u = 0; u < 8; u++) {
        unsigned bn = (unsigned)(k[u] >> 56);
        if (bn < p1)       win[atomicAdd(&s_nwin, 1u)]   = k[u];
        else if (bn == p1) cand1[atomicAdd(&s_nc1, 1u)]  = k[u];
    }
    __syncthreads();

    // ---- level 2: histogram on key bits [55:48] within pivot bin ----
    unsigned need = 48u - base1;   // >= 1 by construction
    hist[tid] = 0;
    __syncthreads();
    unsigned nc1 = s_nc1;
    for (unsigned t = tid; t < nc1; t += 256)
        atomicAdd(&hist[(unsigned)(cand1[t] >> 48) & 255u], 1u);
    __syncthreads();
    scan_pivot(hist, need, &s_pivot, &s_base, tid);
    __syncthreads();
    unsigned p2 = s_pivot;
    for (unsigned t = tid; t < nc1; t += 256) {
        unsigned long long v = cand1[t];
        unsigned bn = (unsigned)(v >> 48) & 255u;
        if (bn < p2)       win[atomicAdd(&s_nwin, 1u)]  = v;
        else if (bn == p2) cand2[atomicAdd(&s_nc2, 1u)] = v;
    }
    __syncthreads();

    // ---- exact extraction of the remaining winners from cand2 ----
    if (wid == 0) {
        int m2 = (int)s_nc2;
        int nw = (int)s_nwin;
        int rem = 48 - nw;        // >= 1
        for (int r = 0; r < rem; r++) {
            unsigned long long best = ~0ull; int bp = -1;
            for (int t = lane; t < m2; t += 32) {
                unsigned long long v = cand2[t];
                if (v < best) { best = v; bp = t; }
            }
#pragma unroll
            for (int off = 16; off > 0; off >>= 1) {
                unsigned long long o = __shfl_xor_sync(0xffffffffu, best, off);
                int op = __shfl_xor_sync(0xffffffffu, bp, off);
                if (o < best) { best = o; bp = op; }
            }
            if (lane == 0) { win[nw + r] = best; cand2[bp] = ~0ull; }
            __syncwarp();
        }
    }
    if (tid >= 48 && tid < 64) win[tid] = ~0ull;
    __syncthreads();

    // ---- exact bitonic sort of 64 slots (48 keys + INF pads), warp 0 ----
    if (wid == 0) {
        unsigned long long a0 = win[2 * lane], a1 = win[2 * lane + 1];
#pragma unroll
        for (int kk = 2; kk <= 64; kk <<= 1) {
#pragma unroll
            for (int j = kk >> 1; j >= 1; j >>= 1) {
                bool up = ((2 * lane) & kk) == 0;
                if (j == 1) {
                    if (up ? (a0 > a1) : (a0 < a1)) {
                        unsigned long long t = a0; a0 = a1; a1 = t;
                    }
                } else {
                    int d = j >> 1;
                    bool lower = (lane & d) == 0;
                    unsigned long long q0 = __shfl_xor_sync(0xffffffffu, a0, d);
                    unsigned long long q1 = __shfl_xor_sync(0xffffffffu, a1, d);
                    bool keepmin = (up == lower);
                    a0 = keepmin ? (a0 < q0 ? a0 : q0) : (a0 > q0 ? a0 : q0);
                    a1 = keepmin ? (a1 < q1 ? a1 : q1) : (a1 > q1 ? a1 : q1);
                }
            }
        }
        size_t baseo = (size_t)(b * LL + i) * KNN;
        int r0 = 2 * lane, r1 = 2 * lane + 1;
        if (r0 < KNN) {
            int j = (int)(unsigned)(a0 & 0xffffffffull);
            g_eidx[baseo + r0] = j;
            if (outI) outI[baseo + r0] = (float)j;
        }
        if (r1 < KNN) {
            int j = (int)(unsigned)(a1 & 0xffffffffull);
            g_eidx[baseo + r1] = j;
            if (outI) outI[baseo + r1] = (float)j;
        }
    }
}

// ---------------------------------------------------------------------------
// Kernel 3 (hot): 2 nodes per CTA (96x128 tile). Software-pipelined:
// iteration c does MMA(c) from A[c&1] while computing features(c+1) into
// A[(c+1)&1] — MUFU/FMA feature work overlaps tensor+LDS MMA work.
// W pre-tf32 via 4-stage cp.async ring. Fused LayerNorm epilogue.
// ---------------------------------------------------------------------------
__global__ void __launch_bounds__(256, 2) edge_kernel(
    const int* __restrict__ ridx, const int* __restrict__ chain,
    const float* __restrict__ Wpos, const float* __restrict__ bpos,
    const float* __restrict__ gamma_, const float* __restrict__ beta_,
    float* __restrict__ outE) {
    extern __shared__ unsigned dsm[];
    __shared__ float ssat[2 * 15];
    __shared__ float snat[96 * 15];
    __shared__ float gam[ED], bet[ED];
    __shared__ float bposs[16];
    __shared__ int   eidx_s[96];
    __shared__ int   dcls[96];

    int tid  = threadIdx.x;
    int wid  = tid >> 5;
    int lane = tid & 31;
    int gid  = lane >> 2, tg = lane & 3;
    int node0 = 2 * blockIdx.x;
    int b = node0 >> 11;

    unsigned smW = smem_u32(dsm) + 2 * AWRD * 4;

    if (tid < ED) { gam[tid] = gamma_[tid]; bet[tid] = beta_[tid]; }
    if (tid < 16) bposs[tid] = bpos[tid];
    if (tid < 96) eidx_s[tid] = g_eidx[(size_t)node0 * KNN + tid];
    if (tid >= 128 && tid < 158) ssat[tid - 128] = g_atoms[(size_t)node0 * 15 + (tid - 128)];
    __syncthreads();

    if (tid < 96) {
        int nl = tid / KNN;
        int j  = eidx_s[tid];
        int ng = node0 + nl;
        int off  = ridx[ng] - ridx[b * LL + j];
        int same = (chain[ng] == chain[b * LL + j]);
        int d = off + 32;
        d = d < 0 ? 0 : (d > 64 ? 64 : d);
        dcls[tid] = same ? d : 65;
    }
    for (int t = tid; t < 96 * 15; t += 256) {
        int n = t / 15, c = t % 15;
        snat[t] = g_atoms[(size_t)(b * LL + eidx_s[n]) * 15 + c];
    }

    // prologue: W chunks 0,1 into ring stages 0,1
#pragma unroll
    for (int q = 0; q < 2; q++) {
        unsigned bst = smW + (unsigned)(q & 3) * WWRD * 4;
#pragma unroll
        for (int e = 0; e < 4; e++) {
            int idx = tid + e * 256;            // 0..1023
            int r = idx >> 5, cgr = idx & 31;   // row 0..31, 16B-granule 0..31
            cp16(bst + (unsigned)(r * WSTR + cgr * 4) * 4,
                 g_Wt + (size_t)(q * 32 + r) * ED + cgr * 4);
        }
        cp_commit();
    }
    __syncthreads();   // snat/ssat/dcls visible before feature compute

    // prologue: features chunk 0 (positional + pair 0) into A stage 0
    {
        unsigned* Ab = dsm;
        if (tid < 96) {
            int row = tid, dc = dcls[row];
#pragma unroll
            for (int j = 0; j < 16; j++)
                Ab[row * ASTR + j] = f2tf(Wpos[dc * 16 + j] + bposs[j]);
        } else if (tid < 192) {
            int row = tid - 96;                 // pair 0 (Ca-Ca)
            int nl = row / KNN;
            float dx = ssat[nl * 15 + 0] - snat[row * 15 + 0];
            float dy = ssat[nl * 15 + 1] - snat[row * 15 + 1];
            float dz = ssat[nl * 15 + 2] - snat[row * 15 + 2];
            float Dp = sqrtf(dx * dx + dy * dy + dz * dz + 1e-6f);
#pragma unroll
            for (int rr = 0; rr < 16; rr++) {
                float mu = 2.0f + (20.0f / 15.0f) * (float)rr;
                float z  = (Dp - mu) * 0.8f;
                Ab[row * ASTR + 16 + rr] = f2tf(__expf(-z * z));
            }
        }
    }

    float acc[3][4][4];
#pragma unroll
    for (int rt = 0; rt < 3; rt++)
#pragma unroll
        for (int j = 0; j < 4; j++)
#pragma unroll
            for (int c = 0; c < 4; c++) acc[rt][j][c] = 0.0f;

    int rg = wid >> 2, cg = wid & 3;
    int rowbase = rg * 48;
    int colbase = cg * 32;

    for (int c = 0; c < NCH; c++) {
        // ---- issue W chunk c+2 into ring stage (c+2)&3 ----
        if (c + 2 < NCH) {
            int q = c + 2;
            unsigned bst = smW + (unsigned)(q & 3) * WWRD * 4;
#pragma unroll
            for (int e = 0; e < 4; e++) {
                int idx = tid + e * 256;
                int r = idx >> 5, cgr = idx & 31;
                cp16(bst + (unsigned)(r * WSTR + cgr * 4) * 4,
                     g_Wt + (size_t)(q * 32 + r) * ED + cgr * 4);
            }
        }
        cp_commit();
        cp_wait2();              // W chunk c landed (this thread's copies)
        __syncthreads();         // A(c) features + everyone's W(c) visible
                                 // (also orders MMA(c-1) reads before
                                 //  features(c+1) writes to the same buffer)

        // ---- MMA on chunk c (reads A[c&1], W[c&3]) ----
        unsigned* Ab = dsm + (c & 1) * AWRD;
        unsigned* Wb = dsm + 2 * AWRD + (c & 3) * WWRD;
#pragma unroll
        for (int s = 0; s < 4; s++) {
            int kb = s * 8;
            unsigned a[3][4];
#pragma unroll
            for (int rt = 0; rt < 3; rt++) {
                int r0 = rowbase + rt * 16 + gid;
                a[rt][0] = Ab[r0 * ASTR + kb + tg];
                a[rt][1] = Ab[(r0 + 8) * ASTR + kb + tg];
                a[rt][2] = Ab[r0 * ASTR + kb + tg + 4];
                a[rt][3] = Ab[(r0 + 8) * ASTR + kb + tg + 4];
            }
            unsigned bf[4][2];
#pragma unroll
            for (int j = 0; j < 4; j++) {
                bf[j][0] = Wb[(kb + tg) * WSTR + colbase + j * 8 + gid];
                bf[j][1] = Wb[(kb + tg + 4) * WSTR + colbase + j * 8 + gid];
            }
#pragma unroll
            for (int rt = 0; rt < 3; rt++)
#pragma unroll
                for (int j = 0; j < 4; j++)
                    MMA_TF32(acc[rt][j], a[rt], bf[j]);
        }

        // ---- overlap: compute features chunk c+1 into A[(c+1)&1] ----
        if (c + 1 < NCH && tid < 192) {
            unsigned* An = dsm + ((c + 1) & 1) * AWRD;
            int pi = tid / 96, row = tid % 96;
            int nl = row / KNN;
            int p  = 2 * (c + 1) - 1 + pi;         // pair 1..24
            int a1 = p / 5, a2 = p % 5;
            float dx = ssat[nl * 15 + a1 * 3 + 0] - snat[row * 15 + a2 * 3 + 0];
            float dy = ssat[nl * 15 + a1 * 3 + 1] - snat[row * 15 + a2 * 3 + 1];
            float dz = ssat[nl * 15 + a1 * 3 + 2] - snat[row * 15 + a2 * 3 + 2];
            float Dp = sqrtf(dx * dx + dy * dy + dz * dz + 1e-6f);
            int cb = 16 * pi;
#pragma unroll
            for (int rr = 0; rr < 16; rr++) {
                float mu = 2.0f + (20.0f / 15.0f) * (float)rr;
                float z  = (Dp - mu) * 0.8f;
                An[row * ASTR + cb + rr] = f2tf(__expf(-z * z));
            }
        }
    }

    // ---- epilogue: stage C (reuse W ring region), LN, store ----
    __syncthreads();
    float* stage = (float*)(dsm + 2 * AWRD);   // 96*132 floats fits in W ring
#pragma unroll
    for (int rt = 0; rt < 3; rt++)
#pragma unroll
        for (int j = 0; j < 4; j++) {
            int row = rowbase + rt * 16 + gid;
            int col = colbase + j * 8 + 2 * tg;
            *(float2*)&stage[row * WSTR + col] =
                make_float2(acc[rt][j][0], acc[rt][j][1]);
            *(float2*)&stage[(row + 8) * WSTR + col] =
                make_float2(acc[rt][j][2], acc[rt][j][3]);
        }
    __syncthreads();

    size_t obase = (size_t)node0 * KNN * ED;
    int tx = tid & 15, ty = tid >> 4;
#pragma unroll
    for (int rr = 0; rr < 6; rr++) {
        int row = ty + 16 * rr;
        float v8[8];
#pragma unroll
        for (int cc = 0; cc < 4; cc++)
            *(float2*)&v8[cc * 2] = *(float2*)&stage[row * WSTR + tx * 8 + cc * 2];
        float s = 0.0f;
#pragma unroll
        for (int cc = 0; cc < 8; cc++) s += v8[cc];
#pragma unroll
        for (int off = 8; off > 0; off >>= 1)
            s += __shfl_xor_sync(0xffffffffu, s, off);
        float mean = s * (1.0f / 128.0f);
        float var = 0.0f;
#pragma unroll
        for (int cc = 0; cc < 8; cc++) { float d = v8[cc] - mean; var += d * d; }
#pragma unroll
        for (int off = 8; off > 0; off >>= 1)
            var += __shfl_xor_sync(0xffffffffu, var, off);
        float rs = rsqrtf(var * (1.0f / 128.0f) + 1e-5f);
        float out[8];
#pragma unroll
        for (int cc = 0; cc < 8; cc++)
            out[cc] = (v8[cc] - mean) * rs * gam[tx * 8 + cc] + bet[tx * 8 + cc];
        float* dst = outE + obase + (size_t)row * ED + tx * 8;
        *(float4*)dst       = make_float4(out[0], out[1], out[2], out[3]);
        *(float4*)(dst + 4) = make_float4(out[4], out[5], out[6], out[7]);
    }
}

// ---------------------------------------------------------------------------
extern "C" void kernel_launch(void* const* d_in, const int* in_sizes, int n_in,
                              void* d_out, int out_size) {
    const float* X     = (const float*)d_in[0];
    const float* mask  = (const float*)d_in[1];
    const int*   ridx  = (const int*)d_in[2];
    const int*   chain = (const int*)d_in[3];
    const float* Wpos  = (const float*)d_in[4];
    const float* bpos  = (const float*)d_in[5];
    const float* Wedge = (const float*)d_in[6];
    const float* gam   = (const float*)d_in[7];
    const float* bet   = (const float*)d_in[8];

    float* outE = (float*)d_out;
    size_t nE = (size_t)BB * LL * KNN * ED;
    float* outI = ((size_t)out_size > nE) ? (outE + nE) : nullptr;

    wt_kernel<<<(416 * ED + 255) / 256, 256>>>(Wedge);
    atoms_kernel<<<(BB * LL + 255) / 256, 256>>>(X);
    topk_kernel<<<BB * LL, 256>>>(X, mask, outI);

    static const int smemK3 = (2 * AWRD + 4 * WWRD) * 4;   // 95232 B
    cudaFuncSetAttribute(edge_kernel,
                         cudaFuncAttributeMaxDynamicSharedMemorySize, smemK3);
    edge_kernel<<<BB * LL / 2, 256, smemK3>>>(ridx, chain, Wpos, bpos,
                                              gam, bet, outE);
    (void)in_sizes; (void)n_in;
}

// round 8
// speedup vs baseline: 4.9346x; 1.2463x over previous
#include <cuda_runtime.h>
#include <cuda_fp16.h>
#include <cstdint>

#define BB   2
#define LL   2048
#define KNN  48
#define ED   128
#define NCH  13            // 13 K-chunks of 32 fp32 cols = K=416

#define ASTR 20            // A smem row stride in u32 (16 half2 + 4 pad)
#define WSTR 132           // W smem row stride in u32 (128 + 4 pad)
#define AWRD (96 * ASTR)   // words per A stage = 1920
#define WWRD (16 * WSTR)   // words per W stage = 2112 (16 k-pair rows)
#define DSMW 12672         // dynamic smem words: epilogue 96*132 staging

// scratch (allocation-free rule: __device__ globals)
__device__ float    g_atoms[BB * LL * 15];
__device__ int      g_eidx[BB * LL * KNN];
__device__ unsigned g_Wh[208 * ED];   // W as half2 k-pairs: [k/2][n]

__device__ __forceinline__ unsigned smem_u32(const void* p) {
    unsigned a;
    asm("{ .reg .u64 t; cvta.to.shared.u64 t, %1; cvt.u32.u64 %0, t; }"
        : "=r"(a) : "l"(p));
    return a;
}
__device__ __forceinline__ void cp16(unsigned dst, const void* src) {
    asm volatile("cp.async.cg.shared.global [%0], [%1], 16;" :: "r"(dst), "l"(src));
}
__device__ __forceinline__ void cp_commit() {
    asm volatile("cp.async.commit_group;" ::: "memory");
}
__device__ __forceinline__ void cp_wait2() {
    asm volatile("cp.async.wait_group 2;" ::: "memory");
}
__device__ __forceinline__ unsigned packh2(float a, float b) {
    __half2 h = __floats2half2_rn(a, b);
    return *(unsigned*)&h;
}

#define MMA_F16(d, a, b)                                                      \
    asm volatile(                                                             \
        "mma.sync.aligned.m16n8k16.row.col.f32.f16.f16.f32 "                  \
        "{%0,%1,%2,%3}, {%4,%5,%6,%7}, {%8,%9}, {%0,%1,%2,%3};"               \
        : "+f"(d[0]), "+f"(d[1]), "+f"(d[2]), "+f"(d[3])                      \
        : "r"(a[0]), "r"(a[1]), "r"(a[2]), "r"(a[3]), "r"(b[0]), "r"(b[1]))

// ---------------------------------------------------------------------------
// Kernel 0: pack W into half2 k-pairs: g_Wh[kk][n] = (h(W[2kk][n]), h(W[2kk+1][n]))
// ---------------------------------------------------------------------------
__global__ void wt_kernel(const float* __restrict__ W) {
    int idx = blockIdx.x * blockDim.x + threadIdx.x;
    if (idx >= 208 * ED) return;
    int kk = idx / ED, n = idx % ED;
    g_Wh[idx] = packh2(W[(2 * kk) * ED + n], W[(2 * kk + 1) * ED + n]);
}

// ---------------------------------------------------------------------------
// Kernel 1: build atoms[Ca,N,C,O,Cb] per residue
// ---------------------------------------------------------------------------
__global__ void atoms_kernel(const float* __restrict__ X) {
    int idx = blockIdx.x * blockDim.x + threadIdx.x;
    if (idx >= BB * LL) return;
    const float* x = X + (size_t)idx * 12;
    float Nx = x[0],  Ny = x[1],  Nz = x[2];
    float Cax = x[3], Cay = x[4], Caz = x[5];
    float Cx = x[6],  Cy = x[7],  Cz = x[8];
    float Ox = x[9],  Oy = x[10], Oz = x[11];

    float bx = Cax - Nx,  by = Cay - Ny,  bz = Caz - Nz;
    float cx = Cx - Cax,  cy = Cy - Cay,  cz = Cz - Caz;
    float ax = by * cz - bz * cy;
    float ay = bz * cx - bx * cz;
    float az = bx * cy - by * cx;
    float Cbx = -0.58273431f * ax + 0.56802827f * bx - 0.54067466f * cx + Cax;
    float Cby = -0.58273431f * ay + 0.56802827f * by - 0.54067466f * cy + Cay;
    float Cbz = -0.58273431f * az + 0.56802827f * bz - 0.54067466f * cz + Caz;

    float* o = g_atoms + (size_t)idx * 15;
    o[0]  = Cax; o[1]  = Cay; o[2]  = Caz;
    o[3]  = Nx;  o[4]  = Ny;  o[5]  = Nz;
    o[6]  = Cx;  o[7]  = Cy;  o[8]  = Cz;
    o[9]  = Ox;  o[10] = Oy;  o[11] = Oz;
    o[12] = Cbx; o[13] = Cby; o[14] = Cbz;
}

// ---------------------------------------------------------------------------
// Radix-select helper (warp 0 scans hist[256] for pivot crossing thr)
// ---------------------------------------------------------------------------
__device__ __forceinline__ void scan_pivot(const unsigned* hist, unsigned thr,
                                           unsigned* s_pivot, unsigned* s_base,
                                           int tid) {
    if (tid < 32) {
        unsigned v[8], pre[8], s = 0;
#pragma unroll
        for (int j = 0; j < 8; j++) { v[j] = hist[tid * 8 + j]; pre[j] = s; s += v[j]; }
        unsigned tot = s, x = tot;
#pragma unroll
        for (int off = 1; off < 32; off <<= 1) {
            unsigned y = __shfl_up_sync(0xffffffffu, x, off);
            if (tid >= off) x += y;
        }
        unsigned ex = x - tot;
        if (ex < thr && ex + tot >= thr) {
#pragma unroll
            for (int j = 0; j < 8; j++) {
                unsigned cb = ex + pre[j];
                if (cb < thr && cb + v[j] >= thr) { *s_pivot = tid * 8 + j; *s_base = cb; }
            }
        }
    }
}

// ---------------------------------------------------------------------------
// Kernel 2: top-K via exact 2-level radix select + extraction + bitonic sort
// ---------------------------------------------------------------------------
__global__ void __launch_bounds__(256) topk_kernel(const float* __restrict__ X,
                                                   const float* __restrict__ mask,
                                                   float* __restrict__ outI) {
    __shared__ __align__(16) char sbuf[32768];
    float* cxs = (float*)sbuf;
    float* cys = cxs + LL;
    float* czs = cys + LL;
    float* mms = czs + LL;
    unsigned long long* cand1 = (unsigned long long*)sbuf;            // 16KB
    unsigned long long* cand2 = (unsigned long long*)(sbuf + 16384);  // 16KB
    __shared__ unsigned hist[256];
    __shared__ unsigned long long win[64];
    __shared__ unsigned s_nwin, s_nc1, s_nc2, s_pivot, s_base;
    __shared__ float wmaxs[8];
    __shared__ float s_dmax;

    int b   = blockIdx.x >> 11;
    int i   = blockIdx.x & (LL - 1);
    int tid = threadIdx.x;
    int lane = tid & 31, wid = tid >> 5;

    for (int t = tid; t < LL; t += 256) {
        const float* p = X + ((size_t)(b * LL + t) * 4 + 1) * 3;   // Ca
        cxs[t] = p[0]; cys[t] = p[1]; czs[t] = p[2];
        mms[t] = mask[b * LL + t];
    }
    __syncthreads();

    float xi = cxs[i], yi = cys[i], zi = czs[i], mi = mms[i];
    float dv[8], m2v[8];
    float dmax = 0.0f;
#pragma unroll
    for (int u = 0; u < 8; u++) {
        int j = tid * 8 + u;
        float dx = __fsub_rn(cxs[j], xi);
        float dy = __fsub_rn(cys[j], yi);
        float dz = __fsub_rn(czs[j], zi);
        float s  = __fadd_rn(__fadd_rn(__fmul_rn(dx, dx), __fmul_rn(dy, dy)),
                             __fmul_rn(dz, dz));
        float dd  = __fsqrt_rn(__fadd_rn(s, 1e-6f));
        float mij = __fmul_rn(mi, mms[j]);
        dv[u]  = __fmul_rn(mij, dd);
        m2v[u] = mij;
        dmax = fmaxf(dmax, dv[u]);
    }
#pragma unroll
    for (int off = 16; off > 0; off >>= 1)
        dmax = fmaxf(dmax, __shfl_xor_sync(0xffffffffu, dmax, off));
    if (lane == 0) wmaxs[wid] = dmax;
    __syncthreads();
    if (tid == 0) {
        float m = wmaxs[0];
        for (int w = 1; w < 8; w++) m = fmaxf(m, wmaxs[w]);
        s_dmax = m;
    }
    __syncthreads();
    float dmx = s_dmax;

    unsigned long long k[8];
#pragma unroll
    for (int u = 0; u < 8; u++) {
        float adj = __fadd_rn(dv[u], __fmul_rn(__fsub_rn(1.0f, m2v[u]), dmx));
        k[u] = ((unsigned long long)__float_as_uint(adj) << 32) |
               (unsigned)(tid * 8 + u);
    }
    __syncthreads();

    hist[tid] = 0;
    if (tid == 0) { s_nwin = 0; s_nc1 = 0; s_nc2 = 0; }
    __syncthreads();
#pragma unroll
    for (int u = 0; u < 8; u++)
        atomicAdd(&hist[(unsigned)(k[u] >> 56)], 1u);
    __syncthreads();
    scan_pivot(hist, 48u, &s_pivot, &s_base, tid);
    __syncthreads();
    unsigned p1 = s_pivot, base1 = s_base;
#pragma unroll
    for (int u = 0; u < 8; u++) {
        unsigned bn = (unsigned)(k[u] >> 56);
        if (bn < p1)       win[atomicAdd(&s_nwin, 1u)]   = k[u];
        else if (bn == p1) cand1[atomicAdd(&s_nc1, 1u)]  = k[u];
    }
    __syncthreads();

    unsigned need = 48u - base1;
    hist[tid] = 0;
    __syncthreads();
    unsigned nc1 = s_nc1;
    for (unsigned t = tid; t < nc1; t += 256)
        atomicAdd(&hist[(unsigned)(cand1[t] >> 48) & 255u], 1u);
    __syncthreads();
    scan_pivot(hist, need, &s_pivot, &s_base, tid);
    __syncthreads();
    unsigned p2 = s_pivot;
    for (unsigned t = tid; t < nc1; t += 256) {
        unsigned long long v = cand1[t];
        unsigned bn = (unsigned)(v >> 48) & 255u;
        if (bn < p2)       win[atomicAdd(&s_nwin, 1u)]  = v;
        else if (bn == p2) cand2[atomicAdd(&s_nc2, 1u)] = v;
    }
    __syncthreads();

    if (wid == 0) {
        int m2 = (int)s_nc2;
        int nw = (int)s_nwin;
        int rem = 48 - nw;
        for (int r = 0; r < rem; r++) {
            unsigned long long best = ~0ull; int bp = -1;
            for (int t = lane; t < m2; t += 32) {
                unsigned long long v = cand2[t];
                if (v < best) { best = v; bp = t; }
            }
#pragma unroll
            for (int off = 16; off > 0; off >>= 1) {
                unsigned long long o = __shfl_xor_sync(0xffffffffu, best, off);
                int op = __shfl_xor_sync(0xffffffffu, bp, off);
                if (o < best) { best = o; bp = op; }
            }
            if (lane == 0) { win[nw + r] = best; cand2[bp] = ~0ull; }
            __syncwarp();
        }
    }
    if (tid >= 48 && tid < 64) win[tid] = ~0ull;
    __syncthreads();

    if (wid == 0) {
        unsigned long long a0 = win[2 * lane], a1 = win[2 * lane + 1];
#pragma unroll
        for (int kk = 2; kk <= 64; kk <<= 1) {
#pragma unroll
            for (int j = kk >> 1; j >= 1; j >>= 1) {
                bool up = ((2 * lane) & kk) == 0;
                if (j == 1) {
                    if (up ? (a0 > a1) : (a0 < a1)) {
                        unsigned long long t = a0; a0 = a1; a1 = t;
                    }
                } else {
                    int d = j >> 1;
                    bool lower = (lane & d) == 0;
                    unsigned long long q0 = __shfl_xor_sync(0xffffffffu, a0, d);
                    unsigned long long q1 = __shfl_xor_sync(0xffffffffu, a1, d);
                    bool keepmin = (up == lower);
                    a0 = keepmin ? (a0 < q0 ? a0 : q0) : (a0 > q0 ? a0 : q0);
                    a1 = keepmin ? (a1 < q1 ? a1 : q1) : (a1 > q1 ? a1 : q1);
                }
            }
        }
        size_t baseo = (size_t)(b * LL + i) * KNN;
        int r0 = 2 * lane, r1 = 2 * lane + 1;
        if (r0 < KNN) {
            int j = (int)(unsigned)(a0 & 0xffffffffull);
            g_eidx[baseo + r0] = j;
            if (outI) outI[baseo + r0] = (float)j;
        }
        if (r1 < KNN) {
            int j = (int)(unsigned)(a1 & 0xffffffffull);
            g_eidx[baseo + r1] = j;
            if (outI) outI[baseo + r1] = (float)j;
        }
    }
}

// ---------------------------------------------------------------------------
// Kernel 3 (hot): 2 nodes per CTA (96x128). fp16 m16n8k16 MMA (fp32 accum):
// same 10-bit mantissa as tf32, HALF the smem bytes. Features half2-packed,
// W half2 k-pairs via 4-stage cp.async ring. Fused LayerNorm epilogue.
// ---------------------------------------------------------------------------
__global__ void __launch_bounds__(256, 2) edge_kernel(
    const int* __restrict__ ridx, const int* __restrict__ chain,
    const float* __restrict__ Wpos, const float* __restrict__ bpos,
    const float* __restrict__ gamma_, const float* __restrict__ beta_,
    float* __restrict__ outE) {
    extern __shared__ unsigned dsm[];
    __shared__ float ssat[2 * 15];
    __shared__ float snat[96 * 15];
    __shared__ float gam[ED], bet[ED];
    __shared__ float bposs[16];
    __shared__ int   eidx_s[96];
    __shared__ int   dcls[96];

    int tid  = threadIdx.x;
    int wid  = tid >> 5;
    int lane = tid & 31;
    int gid  = lane >> 2, tg = lane & 3;
    int node0 = 2 * blockIdx.x;
    int b = node0 >> 11;

    unsigned smW = smem_u32(dsm) + 2 * AWRD * 4;

    if (tid < ED) { gam[tid] = gamma_[tid]; bet[tid] = beta_[tid]; }
    if (tid < 16) bposs[tid] = bpos[tid];
    if (tid < 96) eidx_s[tid] = g_eidx[(size_t)node0 * KNN + tid];
    if (tid >= 128 && tid < 158) ssat[tid - 128] = g_atoms[(size_t)node0 * 15 + (tid - 128)];
    __syncthreads();

    if (tid < 96) {
        int nl = tid / KNN;
        int j  = eidx_s[tid];
        int ng = node0 + nl;
        int off  = ridx[ng] - ridx[b * LL + j];
        int same = (chain[ng] == chain[b * LL + j]);
        int d = off + 32;
        d = d < 0 ? 0 : (d > 64 ? 64 : d);
        dcls[tid] = same ? d : 65;
    }
    for (int t = tid; t < 96 * 15; t += 256) {
        int n = t / 15, c = t % 15;
        snat[t] = g_atoms[(size_t)(b * LL + eidx_s[n]) * 15 + c];
    }

    // prologue: W chunks 0,1 into ring stages 0,1 (8KB each, 2 cp16/thread)
#pragma unroll
    for (int q = 0; q < 2; q++) {
        unsigned bst = smW + (unsigned)(q & 3) * WWRD * 4;
#pragma unroll
        for (int e = 0; e < 2; e++) {
            int idx = tid + e * 256;            // 0..511
            int r = idx >> 5, g = idx & 31;     // k-pair row 0..15, granule 0..31
            cp16(bst + (unsigned)(r * WSTR + g * 4) * 4,
                 g_Wh + (size_t)(q * 16 + r) * ED + g * 4);
        }
        cp_commit();
    }
    __syncthreads();   // snat/ssat/dcls visible before feature compute

    // prologue: features chunk 0 (positional + pair 0) into A stage 0
    {
        unsigned* Ab = dsm;
        if (tid < 96) {
            int row = tid, dc = dcls[row];
#pragma unroll
            for (int q = 0; q < 8; q++)
                Ab[row * ASTR + q] = packh2(Wpos[dc * 16 + 2 * q]     + bposs[2 * q],
                                            Wpos[dc * 16 + 2 * q + 1] + bposs[2 * q + 1]);
        } else if (tid < 192) {
            int row = tid - 96;                 // pair 0 (Ca-Ca)
            int nl = row / KNN;
            float dx = ssat[nl * 15 + 0] - snat[row * 15 + 0];
            float dy = ssat[nl * 15 + 1] - snat[row * 15 + 1];
            float dz = ssat[nl * 15 + 2] - snat[row * 15 + 2];
            float Dp = sqrtf(dx * dx + dy * dy + dz * dz + 1e-6f);
#pragma unroll
            for (int q = 0; q < 8; q++) {
                float mu0 = 2.0f + (20.0f / 15.0f) * (float)(2 * q);
                float mu1 = 2.0f + (20.0f / 15.0f) * (float)(2 * q + 1);
                float z0 = (Dp - mu0) * 0.8f, z1 = (Dp - mu1) * 0.8f;
                Ab[row * ASTR + 8 + q] = packh2(__expf(-z0 * z0), __expf(-z1 * z1));
            }
        }
    }

    float acc[3][4][4];
#pragma unroll
    for (int rt = 0; rt < 3; rt++)
#pragma unroll
        for (int j = 0; j < 4; j++)
#pragma unroll
            for (int c = 0; c < 4; c++) acc[rt][j][c] = 0.0f;

    int rg = wid >> 2, cg = wid & 3;
    int rowbase = rg * 48;
    int colbase = cg * 32;

    for (int c = 0; c < NCH; c++) {
        // ---- issue W chunk c+2 into ring stage (c+2)&3 ----
        if (c + 2 < NCH) {
            int q = c + 2;
            unsigned bst = smW + (unsigned)(q & 3) * WWRD * 4;
#pragma unroll
            for (int e = 0; e < 2; e++) {
                int idx = tid + e * 256;
                int r = idx >> 5, g = idx & 31;
                cp16(bst + (unsigned)(r * WSTR + g * 4) * 4,
                     g_Wh + (size_t)(q * 16 + r) * ED + g * 4);
            }
        }
        cp_commit();
        cp_wait2();              // W chunk c landed
        __syncthreads();         // A(c) features + W(c) visible; orders
                                 // MMA(c-1) reads before features(c+1) writes

        // ---- MMA on chunk c: 2 k16 steps (reads A[c&1], W[c&3]) ----
        unsigned* Ab = dsm + (c & 1) * AWRD;
        unsigned* Wb = dsm + 2 * AWRD + (c & 3) * WWRD;
#pragma unroll
        for (int s = 0; s < 2; s++) {
            int kb = s * 8;      // u32 (half2) column base
            unsigned a[3][4];
#pragma unroll
            for (int rt = 0; rt < 3; rt++) {
                int r0 = rowbase + rt * 16 + gid;
                a[rt][0] = Ab[r0 * ASTR + kb + tg];
                a[rt][1] = Ab[(r0 + 8) * ASTR + kb + tg];
                a[rt][2] = Ab[r0 * ASTR + kb + tg + 4];
                a[rt][3] = Ab[(r0 + 8) * ASTR + kb + tg + 4];
            }
            unsigned bf[4][2];
#pragma unroll
            for (int j = 0; j < 4; j++) {
                bf[j][0] = Wb[(kb + tg) * WSTR + colbase + j * 8 + gid];
                bf[j][1] = Wb[(kb + tg + 4) * WSTR + colbase + j * 8 + gid];
            }
#pragma unroll
            for (int rt = 0; rt < 3; rt++)
#pragma unroll
                for (int j = 0; j < 4; j++)
                    MMA_F16(acc[rt][j], a[rt], bf[j]);
        }

        // ---- overlap: compute features chunk c+1 into A[(c+1)&1] ----
        if (c + 1 < NCH && tid < 192) {
            unsigned* An = dsm + ((c + 1) & 1) * AWRD;
            int pi = tid / 96, row = tid % 96;
            int nl = row / KNN;
            int p  = 2 * (c + 1) - 1 + pi;         // pair 1..24
            int a1 = p / 5, a2 = p % 5;
            float dx = ssat[nl * 15 + a1 * 3 + 0] - snat[row * 15 + a2 * 3 + 0];
            float dy = ssat[nl * 15 + a1 * 3 + 1] - snat[row * 15 + a2 * 3 + 1];
            float dz = ssat[nl * 15 + a1 * 3 + 2] - snat[row * 15 + a2 * 3 + 2];
            float Dp = sqrtf(dx * dx + dy * dy + dz * dz + 1e-6f);
            int cb = 8 * pi;
#pragma unroll
            for (int q = 0; q < 8; q++) {
                float mu0 = 2.0f + (20.0f / 15.0f) * (float)(2 * q);
                float mu1 = 2.0f + (20.0f / 15.0f) * (float)(2 * q + 1);
                float z0 = (Dp - mu0) * 0.8f, z1 = (Dp - mu1) * 0.8f;
                An[row * ASTR + cb + q] = packh2(__expf(-z0 * z0), __expf(-z1 * z1));
            }
        }
    }

    // ---- epilogue: stage C into dsm (whole buffer free now), LN, store ----
    __syncthreads();
    float* stage = (float*)dsm;    // 96*132 floats = 12672 words = DSMW
#pragma unroll
    for (int rt = 0; rt < 3; rt++)
#pragma unroll
        for (int j = 0; j < 4; j++) {
            int row = rowbase + rt * 16 + gid;
            int col = colbase + j * 8 + 2 * tg;
            *(float2*)&stage[row * WSTR + col] =
                make_float2(acc[rt][j][0], acc[rt][j][1]);
            *(float2*)&stage[(row + 8) * WSTR + col] =
                make_float2(acc[rt][j][2], acc[rt][j][3]);
        }
    __syncthreads();

    size_t obase = (size_t)node0 * KNN * ED;
    int tx = tid & 15, ty = tid >> 4;
#pragma unroll
    for (int rr = 0; rr < 6; rr++) {
        int row = ty + 16 * rr;
        float v8[8];
#pragma unroll
        for (int cc = 0; cc < 4; cc++)
            *(float2*)&v8[cc * 2] = *(float2*)&stage[row * WSTR + tx * 8 + cc * 2];
        float s = 0.0f;
#pragma unroll
        for (int cc = 0; cc < 8; cc++) s += v8[cc];
#pragma unroll
        for (int off = 8; off > 0; off >>= 1)
            s += __shfl_xor_sync(0xffffffffu, s, off);
        float mean = s * (1.0f / 128.0f);
        float var = 0.0f;
#pragma unroll
        for (int cc = 0; cc < 8; cc++) { float d = v8[cc] - mean; var += d * d; }
#pragma unroll
        for (int off = 8; off > 0; off >>= 1)
            var += __shfl_xor_sync(0xffffffffu, var, off);
        float rs = rsqrtf(var * (1.0f / 128.0f) + 1e-5f);
        float out[8];
#pragma unroll
        for (int cc = 0; cc < 8; cc++)
            out[cc] = (v8[cc] - mean) * rs * gam[tx * 8 + cc] + bet[tx * 8 + cc];
        float* dst = outE + obase + (size_t)row * ED + tx * 8;
        *(float4*)dst       = make_float4(out[0], out[1], out[2], out[3]);
        *(float4*)(dst + 4) = make_float4(out[4], out[5], out[6], out[7]);
    }
}

// ---------------------------------------------------------------------------
extern "C" void kernel_launch(void* const* d_in, const int* in_sizes, int n_in,
                              void* d_out, int out_size) {
    const float* X     = (const float*)d_in[0];
    const float* mask  = (const float*)d_in[1];
    const int*   ridx  = (const int*)d_in[2];
    const int*   chain = (const int*)d_in[3];
    const float* Wpos  = (const float*)d_in[4];
    const float* bpos  = (const float*)d_in[5];
    const float* Wedge = (const float*)d_in[6];
    const float* gam   = (const float*)d_in[7];
    const float* bet   = (const float*)d_in[8];

    float* outE = (float*)d_out;
    size_t nE = (size_t)BB * LL * KNN * ED;
    float* outI = ((size_t)out_size > nE) ? (outE + nE) : nullptr;

    wt_kernel<<<(208 * ED + 255) / 256, 256>>>(Wedge);
    atoms_kernel<<<(BB * LL + 255) / 256, 256>>>(X);
    topk_kernel<<<BB * LL, 256>>>(X, mask, outI);

    static const int smemK3 = DSMW * 4;   // 50688 B (epilogue staging bound)
    cudaFuncSetAttribute(edge_kernel,
                         cudaFuncAttributeMaxDynamicSharedMemorySize, smemK3);
    edge_kernel<<<BB * LL / 2, 256, smemK3>>>(ridx, chain, Wpos, bpos,
                                              gam, bet, outE);
    (void)in_sizes; (void)n_in;
}

// round 9
// speedup vs baseline: 5.7209x; 1.1593x over previous
#include <cuda_runtime.h>
#include <cuda_fp16.h>
#include <cstdint>

#define BB   2
#define LL   2048
#define KNN  48
#define ED   128
#define NCH  13            // 13 K-chunks of 32 fp32 cols = K=416

#define ASTR 20            // A smem row stride in u32 (16 half2 + 4 pad)
#define WSTR 132           // W smem row stride in u32 (128 + 4 pad)
#define AWRD (96 * ASTR)   // words per A stage = 1920
#define WWRD (16 * WSTR)   // words per W stage = 2112 (16 k-pair rows)
#define DSMW (2 * AWRD + 4 * WWRD)   // 12288 words = 49152 B

// scratch (allocation-free rule: __device__ globals)
__device__ float    g_atoms[BB * LL * 15];
__device__ int      g_eidx[BB * LL * KNN];
__device__ unsigned g_Wh[208 * ED];   // W as half2 k-pairs: [k/2][n]

__device__ __forceinline__ unsigned smem_u32(const void* p) {
    unsigned a;
    asm("{ .reg .u64 t; cvta.to.shared.u64 t, %1; cvt.u32.u64 %0, t; }"
        : "=r"(a) : "l"(p));
    return a;
}
__device__ __forceinline__ void cp16(unsigned dst, const void* src) {
    asm volatile("cp.async.cg.shared.global [%0], [%1], 16;" :: "r"(dst), "l"(src));
}
__device__ __forceinline__ void cp_commit() {
    asm volatile("cp.async.commit_group;" ::: "memory");
}
__device__ __forceinline__ void cp_wait2() {
    asm volatile("cp.async.wait_group 2;" ::: "memory");
}
__device__ __forceinline__ unsigned packh2(float a, float b) {
    __half2 h = __floats2half2_rn(a, b);
    return *(unsigned*)&h;
}

#define MMA_F16(d, a, b)                                                      \
    asm volatile(                                                             \
        "mma.sync.aligned.m16n8k16.row.col.f32.f16.f16.f32 "                  \
        "{%0,%1,%2,%3}, {%4,%5,%6,%7}, {%8,%9}, {%0,%1,%2,%3};"               \
        : "+f"(d[0]), "+f"(d[1]), "+f"(d[2]), "+f"(d[3])                      \
        : "r"(a[0]), "r"(a[1]), "r"(a[2]), "r"(a[3]), "r"(b[0]), "r"(b[1]))

// ---------------------------------------------------------------------------
// Kernel 0: pack W into half2 k-pairs: g_Wh[kk][n] = (h(W[2kk][n]), h(W[2kk+1][n]))
// ---------------------------------------------------------------------------
__global__ void wt_kernel(const float* __restrict__ W) {
    int idx = blockIdx.x * blockDim.x + threadIdx.x;
    if (idx >= 208 * ED) return;
    int kk = idx / ED, n = idx % ED;
    g_Wh[idx] = packh2(W[(2 * kk) * ED + n], W[(2 * kk + 1) * ED + n]);
}

// ---------------------------------------------------------------------------
// Kernel 1: build atoms[Ca,N,C,O,Cb] per residue
// ---------------------------------------------------------------------------
__global__ void atoms_kernel(const float* __restrict__ X) {
    int idx = blockIdx.x * blockDim.x + threadIdx.x;
    if (idx >= BB * LL) return;
    const float* x = X + (size_t)idx * 12;
    float Nx = x[0],  Ny = x[1],  Nz = x[2];
    float Cax = x[3], Cay = x[4], Caz = x[5];
    float Cx = x[6],  Cy = x[7],  Cz = x[8];
    float Ox = x[9],  Oy = x[10], Oz = x[11];

    float bx = Cax - Nx,  by = Cay - Ny,  bz = Caz - Nz;
    float cx = Cx - Cax,  cy = Cy - Cay,  cz = Cz - Caz;
    float ax = by * cz - bz * cy;
    float ay = bz * cx - bx * cz;
    float az = bx * cy - by * cx;
    float Cbx = -0.58273431f * ax + 0.56802827f * bx - 0.54067466f * cx + Cax;
    float Cby = -0.58273431f * ay + 0.56802827f * by - 0.54067466f * cy + Cay;
    float Cbz = -0.58273431f * az + 0.56802827f * bz - 0.54067466f * cz + Caz;

    float* o = g_atoms + (size_t)idx * 15;
    o[0]  = Cax; o[1]  = Cay; o[2]  = Caz;
    o[3]  = Nx;  o[4]  = Ny;  o[5]  = Nz;
    o[6]  = Cx;  o[7]  = Cy;  o[8]  = Cz;
    o[9]  = Ox;  o[10] = Oy;  o[11] = Oz;
    o[12] = Cbx; o[13] = Cby; o[14] = Cbz;
}

// ---------------------------------------------------------------------------
// Radix-select helper (warp 0 scans hist[256] for pivot crossing thr)
// ---------------------------------------------------------------------------
__device__ __forceinline__ void scan_pivot(const unsigned* hist, unsigned thr,
                                           unsigned* s_pivot, unsigned* s_base,
                                           int tid) {
    if (tid < 32) {
        unsigned v[8], pre[8], s = 0;
#pragma unroll
        for (int j = 0; j < 8; j++) { v[j] = hist[tid * 8 + j]; pre[j] = s; s += v[j]; }
        unsigned tot = s, x = tot;
#pragma unroll
        for (int off = 1; off < 32; off <<= 1) {
            unsigned y = __shfl_up_sync(0xffffffffu, x, off);
            if (tid >= off) x += y;
        }
        unsigned ex = x - tot;
        if (ex < thr && ex + tot >= thr) {
#pragma unroll
            for (int j = 0; j < 8; j++) {
                unsigned cb = ex + pre[j];
                if (cb < thr && cb + v[j] >= thr) { *s_pivot = tid * 8 + j; *s_base = cb; }
            }
        }
    }
}

// ---------------------------------------------------------------------------
// Kernel 2: top-K via exact 2-level radix select + extraction + bitonic sort
// ---------------------------------------------------------------------------
__global__ void __launch_bounds__(256) topk_kernel(const float* __restrict__ X,
                                                   const float* __restrict__ mask,
                                                   float* __restrict__ outI) {
    __shared__ __align__(16) char sbuf[32768];
    float* cxs = (float*)sbuf;
    float* cys = cxs + LL;
    float* czs = cys + LL;
    float* mms = czs + LL;
    unsigned long long* cand1 = (unsigned long long*)sbuf;            // 16KB
    unsigned long long* cand2 = (unsigned long long*)(sbuf + 16384);  // 16KB
    __shared__ unsigned hist[256];
    __shared__ unsigned long long win[64];
    __shared__ unsigned s_nwin, s_nc1, s_nc2, s_pivot, s_base;
    __shared__ float wmaxs[8];
    __shared__ float s_dmax;

    int b   = blockIdx.x >> 11;
    int i   = blockIdx.x & (LL - 1);
    int tid = threadIdx.x;
    int lane = tid & 31, wid = tid >> 5;

    for (int t = tid; t < LL; t += 256) {
        const float* p = X + ((size_t)(b * LL + t) * 4 + 1) * 3;   // Ca
        cxs[t] = p[0]; cys[t] = p[1]; czs[t] = p[2];
        mms[t] = mask[b * LL + t];
    }
    __syncthreads();

    float xi = cxs[i], yi = cys[i], zi = czs[i], mi = mms[i];
    float dv[8], m2v[8];
    float dmax = 0.0f;
#pragma unroll
    for (int u = 0; u < 8; u++) {
        int j = tid * 8 + u;
        float dx = __fsub_rn(cxs[j], xi);
        float dy = __fsub_rn(cys[j], yi);
        float dz = __fsub_rn(czs[j], zi);
        float s  = __fadd_rn(__fadd_rn(__fmul_rn(dx, dx), __fmul_rn(dy, dy)),
                             __fmul_rn(dz, dz));
        float dd  = __fsqrt_rn(__fadd_rn(s, 1e-6f));
        float mij = __fmul_rn(mi, mms[j]);
        dv[u]  = __fmul_rn(mij, dd);
        m2v[u] = mij;
        dmax = fmaxf(dmax, dv[u]);
    }
#pragma unroll
    for (int off = 16; off > 0; off >>= 1)
        dmax = fmaxf(dmax, __shfl_xor_sync(0xffffffffu, dmax, off));
    if (lane == 0) wmaxs[wid] = dmax;
    __syncthreads();
    if (tid == 0) {
        float m = wmaxs[0];
        for (int w = 1; w < 8; w++) m = fmaxf(m, wmaxs[w]);
        s_dmax = m;
    }
    __syncthreads();
    float dmx = s_dmax;

    unsigned long long k[8];
#pragma unroll
    for (int u = 0; u < 8; u++) {
        float adj = __fadd_rn(dv[u], __fmul_rn(__fsub_rn(1.0f, m2v[u]), dmx));
        k[u] = ((unsigned long long)__float_as_uint(adj) << 32) |
               (unsigned)(tid * 8 + u);
    }
    __syncthreads();

    hist[tid] = 0;
    if (tid == 0) { s_nwin = 0; s_nc1 = 0; s_nc2 = 0; }
    __syncthreads();
#pragma unroll
    for (int u = 0; u < 8; u++)
        atomicAdd(&hist[(unsigned)(k[u] >> 56)], 1u);
    __syncthreads();
    scan_pivot(hist, 48u, &s_pivot, &s_base, tid);
    __syncthreads();
    unsigned p1 = s_pivot, base1 = s_base;
#pragma unroll
    for (int u = 0; u < 8; u++) {
        unsigned bn = (unsigned)(k[u] >> 56);
        if (bn < p1)       win[atomicAdd(&s_nwin, 1u)]   = k[u];
        else if (bn == p1) cand1[atomicAdd(&s_nc1, 1u)]  = k[u];
    }
    __syncthreads();

    unsigned need = 48u - base1;
    hist[tid] = 0;
    __syncthreads();
    unsigned nc1 = s_nc1;
    for (unsigned t = tid; t < nc1; t += 256)
        atomicAdd(&hist[(unsigned)(cand1[t] >> 48) & 255u], 1u);
    __syncthreads();
    scan_pivot(hist, need, &s_pivot, &s_base, tid);
    __syncthreads();
    unsigned p2 = s_pivot;
    for (unsigned t = tid; t < nc1; t += 256) {
        unsigned long long v = cand1[t];
        unsigned bn = (unsigned)(v >> 48) & 255u;
        if (bn < p2)       win[atomicAdd(&s_nwin, 1u)]  = v;
        else if (bn == p2) cand2[atomicAdd(&s_nc2, 1u)] = v;
    }
    __syncthreads();

    if (wid == 0) {
        int m2 = (int)s_nc2;
        int nw = (int)s_nwin;
        int rem = 48 - nw;
        for (int r = 0; r < rem; r++) {
            unsigned long long best = ~0ull; int bp = -1;
            for (int t = lane; t < m2; t += 32) {
                unsigned long long v = cand2[t];
                if (v < best) { best = v; bp = t; }
            }
#pragma unroll
            for (int off = 16; off > 0; off >>= 1) {
                unsigned long long o = __shfl_xor_sync(0xffffffffu, best, off);
                int op = __shfl_xor_sync(0xffffffffu, bp, off);
                if (o < best) { best = o; bp = op; }
            }
            if (lane == 0) { win[nw + r] = best; cand2[bp] = ~0ull; }
            __syncwarp();
        }
    }
    if (tid >= 48 && tid < 64) win[tid] = ~0ull;
    __syncthreads();

    if (wid == 0) {
        unsigned long long a0 = win[2 * lane], a1 = win[2 * lane + 1];
#pragma unroll
        for (int kk = 2; kk <= 64; kk <<= 1) {
#pragma unroll
            for (int j = kk >> 1; j >= 1; j >>= 1) {
                bool up = ((2 * lane) & kk) == 0;
                if (j == 1) {
                    if (up ? (a0 > a1) : (a0 < a1)) {
                        unsigned long long t = a0; a0 = a1; a1 = t;
                    }
                } else {
                    int d = j >> 1;
                    bool lower = (lane & d) == 0;
                    unsigned long long q0 = __shfl_xor_sync(0xffffffffu, a0, d);
                    unsigned long long q1 = __shfl_xor_sync(0xffffffffu, a1, d);
                    bool keepmin = (up == lower);
                    a0 = keepmin ? (a0 < q0 ? a0 : q0) : (a0 > q0 ? a0 : q0);
                    a1 = keepmin ? (a1 < q1 ? a1 : q1) : (a1 > q1 ? a1 : q1);
                }
            }
        }
        size_t baseo = (size_t)(b * LL + i) * KNN;
        int r0 = 2 * lane, r1 = 2 * lane + 1;
        if (r0 < KNN) {
            int j = (int)(unsigned)(a0 & 0xffffffffull);
            g_eidx[baseo + r0] = j;
            if (outI) outI[baseo + r0] = (float)j;
        }
        if (r1 < KNN) {
            int j = (int)(unsigned)(a1 & 0xffffffffull);
            g_eidx[baseo + r1] = j;
            if (outI) outI[baseo + r1] = (float)j;
        }
    }
}

// ---------------------------------------------------------------------------
// Kernel 3 (hot): 2 nodes per CTA (96x128). fp16 m16n8k16 MMA (fp32 accum).
// Direct-store LN epilogue: per-row (sum,sumsq) partials exchanged via 3KB
// smem, fragments normalized in registers, float2 stores straight to gmem.
// __launch_bounds__(256,3): regs<=85 -> 3 CTAs/SM for latency hiding.
// ---------------------------------------------------------------------------
__global__ void __launch_bounds__(256, 3) edge_kernel(
    const int* __restrict__ ridx, const int* __restrict__ chain,
    const float* __restrict__ Wpos, const float* __restrict__ bpos,
    const float* __restrict__ gamma_, const float* __restrict__ beta_,
    float* __restrict__ outE) {
    extern __shared__ unsigned dsm[];
    __shared__ float ssat[2 * 15];
    __shared__ float snat[96 * 15];
    __shared__ float gam[ED], bet[ED];
    __shared__ float bposs[16];
    __shared__ int   eidx_s[96];
    __shared__ int   dcls[96];
    __shared__ float2 psum[96][4];     // per-(row, colgroup) partial (sum, sumsq)

    int tid  = threadIdx.x;
    int wid  = tid >> 5;
    int lane = tid & 31;
    int gid  = lane >> 2, tg = lane & 3;
    int node0 = 2 * blockIdx.x;
    int b = node0 >> 11;

    unsigned smW = smem_u32(dsm) + 2 * AWRD * 4;

    if (tid < ED) { gam[tid] = gamma_[tid]; bet[tid] = beta_[tid]; }
    if (tid < 16) bposs[tid] = bpos[tid];
    if (tid < 96) eidx_s[tid] = g_eidx[(size_t)node0 * KNN + tid];
    if (tid >= 128 && tid < 158) ssat[tid - 128] = g_atoms[(size_t)node0 * 15 + (tid - 128)];
    __syncthreads();

    if (tid < 96) {
        int nl = tid / KNN;
        int j  = eidx_s[tid];
        int ng = node0 + nl;
        int off  = ridx[ng] - ridx[b * LL + j];
        int same = (chain[ng] == chain[b * LL + j]);
        int d = off + 32;
        d = d < 0 ? 0 : (d > 64 ? 64 : d);
        dcls[tid] = same ? d : 65;
    }
    for (int t = tid; t < 96 * 15; t += 256) {
        int n = t / 15, c = t % 15;
        snat[t] = g_atoms[(size_t)(b * LL + eidx_s[n]) * 15 + c];
    }

    // prologue: W chunks 0,1 into ring stages 0,1 (8KB each, 2 cp16/thread)
#pragma unroll
    for (int q = 0; q < 2; q++) {
        unsigned bst = smW + (unsigned)(q & 3) * WWRD * 4;
#pragma unroll
        for (int e = 0; e < 2; e++) {
            int idx = tid + e * 256;            // 0..511
            int r = idx >> 5, g = idx & 31;     // k-pair row 0..15, granule 0..31
            cp16(bst + (unsigned)(r * WSTR + g * 4) * 4,
                 g_Wh + (size_t)(q * 16 + r) * ED + g * 4);
        }
        cp_commit();
    }
    __syncthreads();   // snat/ssat/dcls visible before feature compute

    // prologue: features chunk 0 (positional + pair 0) into A stage 0
    {
        unsigned* Ab = dsm;
        if (tid < 96) {
            int row = tid, dc = dcls[row];
#pragma unroll
            for (int q = 0; q < 8; q++)
                Ab[row * ASTR + q] = packh2(Wpos[dc * 16 + 2 * q]     + bposs[2 * q],
                                            Wpos[dc * 16 + 2 * q + 1] + bposs[2 * q + 1]);
        } else if (tid < 192) {
            int row = tid - 96;                 // pair 0 (Ca-Ca)
            int nl = row / KNN;
            float dx = ssat[nl * 15 + 0] - snat[row * 15 + 0];
            float dy = ssat[nl * 15 + 1] - snat[row * 15 + 1];
            float dz = ssat[nl * 15 + 2] - snat[row * 15 + 2];
            float Dp = sqrtf(dx * dx + dy * dy + dz * dz + 1e-6f);
#pragma unroll
            for (int q = 0; q < 8; q++) {
                float mu0 = 2.0f + (20.0f / 15.0f) * (float)(2 * q);
                float mu1 = 2.0f + (20.0f / 15.0f) * (float)(2 * q + 1);
                float z0 = (Dp - mu0) * 0.8f, z1 = (Dp - mu1) * 0.8f;
                Ab[row * ASTR + 8 + q] = packh2(__expf(-z0 * z0), __expf(-z1 * z1));
            }
        }
    }

    float acc[3][4][4];
#pragma unroll
    for (int rt = 0; rt < 3; rt++)
#pragma unroll
        for (int j = 0; j < 4; j++)
#pragma unroll
            for (int c = 0; c < 4; c++) acc[rt][j][c] = 0.0f;

    int rg = wid >> 2, cg = wid & 3;
    int rowbase = rg * 48;
    int colbase = cg * 32;

    for (int c = 0; c < NCH; c++) {
        // ---- issue W chunk c+2 into ring stage (c+2)&3 ----
        if (c + 2 < NCH) {
            int q = c + 2;
            unsigned bst = smW + (unsigned)(q & 3) * WWRD * 4;
#pragma unroll
            for (int e = 0; e < 2; e++) {
                int idx = tid + e * 256;
                int r = idx >> 5, g = idx & 31;
                cp16(bst + (unsigned)(r * WSTR + g * 4) * 4,
                     g_Wh + (size_t)(q * 16 + r) * ED + g * 4);
            }
        }
        cp_commit();
        cp_wait2();              // W chunk c landed
        __syncthreads();         // A(c) features + W(c) visible; orders
                                 // MMA(c-1) reads before features(c+1) writes

        // ---- MMA on chunk c: 2 k16 steps (reads A[c&1], W[c&3]) ----
        unsigned* Ab = dsm + (c & 1) * AWRD;
        unsigned* Wb = dsm + 2 * AWRD + (c & 3) * WWRD;
#pragma unroll
        for (int s = 0; s < 2; s++) {
            int kb = s * 8;      // u32 (half2) column base
            unsigned a[3][4];
#pragma unroll
            for (int rt = 0; rt < 3; rt++) {
                int r0 = rowbase + rt * 16 + gid;
                a[rt][0] = Ab[r0 * ASTR + kb + tg];
                a[rt][1] = Ab[(r0 + 8) * ASTR + kb + tg];
                a[rt][2] = Ab[r0 * ASTR + kb + tg + 4];
                a[rt][3] = Ab[(r0 + 8) * ASTR + kb + tg + 4];
            }
            unsigned bf[4][2];
#pragma unroll
            for (int j = 0; j < 4; j++) {
                bf[j][0] = Wb[(kb + tg) * WSTR + colbase + j * 8 + gid];
                bf[j][1] = Wb[(kb + tg + 4) * WSTR + colbase + j * 8 + gid];
            }
#pragma unroll
            for (int rt = 0; rt < 3; rt++)
#pragma unroll
                for (int j = 0; j < 4; j++)
                    MMA_F16(acc[rt][j], a[rt], bf[j]);
        }

        // ---- overlap: compute features chunk c+1 into A[(c+1)&1] ----
        if (c + 1 < NCH && tid < 192) {
            unsigned* An = dsm + ((c + 1) & 1) * AWRD;
            int pi = tid / 96, row = tid % 96;
            int nl = row / KNN;
            int p  = 2 * (c + 1) - 1 + pi;         // pair 1..24
            int a1 = p / 5, a2 = p % 5;
            float dx = ssat[nl * 15 + a1 * 3 + 0] - snat[row * 15 + a2 * 3 + 0];
            float dy = ssat[nl * 15 + a1 * 3 + 1] - snat[row * 15 + a2 * 3 + 1];
            float dz = ssat[nl * 15 + a1 * 3 + 2] - snat[row * 15 + a2 * 3 + 2];
            float Dp = sqrtf(dx * dx + dy * dy + dz * dz + 1e-6f);
            int cb = 8 * pi;
#pragma unroll
            for (int q = 0; q < 8; q++) {
                float mu0 = 2.0f + (20.0f / 15.0f) * (float)(2 * q);
                float mu1 = 2.0f + (20.0f / 15.0f) * (float)(2 * q + 1);
                float z0 = (Dp - mu0) * 0.8f, z1 = (Dp - mu1) * 0.8f;
                An[row * ASTR + cb + q] = packh2(__expf(-z0 * z0), __expf(-z1 * z1));
            }
        }
    }

    // ---- epilogue: per-row partials across the 4 colgroup warps ----
#pragma unroll
    for (int rt = 0; rt < 3; rt++) {
        float s0 = 0.f, q0 = 0.f, s1 = 0.f, q1 = 0.f;
#pragma unroll
        for (int j = 0; j < 4; j++) {
            s0 += acc[rt][j][0] + acc[rt][j][1];
            q0 += acc[rt][j][0] * acc[rt][j][0] + acc[rt][j][1] * acc[rt][j][1];
            s1 += acc[rt][j][2] + acc[rt][j][3];
            q1 += acc[rt][j][2] * acc[rt][j][2] + acc[rt][j][3] * acc[rt][j][3];
        }
#pragma unroll
        for (int m = 1; m <= 2; m <<= 1) {
            s0 += __shfl_xor_sync(0xffffffffu, s0, m);
            q0 += __shfl_xor_sync(0xffffffffu, q0, m);
            s1 += __shfl_xor_sync(0xffffffffu, s1, m);
            q1 += __shfl_xor_sync(0xffffffffu, q1, m);
        }
        if (tg == 0) {
            int r0 = rowbase + rt * 16 + gid;
            psum[r0][cg]     = make_float2(s0, q0);
            psum[r0 + 8][cg] = make_float2(s1, q1);
        }
    }
    __syncthreads();

    // ---- LN in registers + direct float2 stores to gmem ----
    size_t obase = (size_t)node0 * KNN * ED;
#pragma unroll
    for (int rt = 0; rt < 3; rt++) {
        int r0 = rowbase + rt * 16 + gid;
        float2 pa0 = psum[r0][0], pa1 = psum[r0][1];
        float2 pa2 = psum[r0][2], pa3 = psum[r0][3];
        float2 pb0 = psum[r0 + 8][0], pb1 = psum[r0 + 8][1];
        float2 pb2 = psum[r0 + 8][2], pb3 = psum[r0 + 8][3];
        float mean0 = (pa0.x + pa1.x + pa2.x + pa3.x) * (1.0f / 128.0f);
        float var0  = (pa0.y + pa1.y + pa2.y + pa3.y) * (1.0f / 128.0f) - mean0 * mean0;
        float rs0   = rsqrtf(var0 + 1e-5f);
        float mean1 = (pb0.x + pb1.x + pb2.x + pb3.x) * (1.0f / 128.0f);
        float var1  = (pb0.y + pb1.y + pb2.y + pb3.y) * (1.0f / 128.0f) - mean1 * mean1;
        float rs1   = rsqrtf(var1 + 1e-5f);
        float* dst0 = outE + obase + (size_t)r0 * ED;
        float* dst1 = dst0 + 8 * ED;
#pragma unroll
        for (int j = 0; j < 4; j++) {
            int col = colbase + j * 8 + 2 * tg;
            float g0 = gam[col], g1 = gam[col + 1];
            float b0 = bet[col], b1 = bet[col + 1];
            *(float2*)(dst0 + col) =
                make_float2((acc[rt][j][0] - mean0) * rs0 * g0 + b0,
                            (acc[rt][j][1] - mean0) * rs0 * g1 + b1);
            *(float2*)(dst1 + col) =
                make_float2((acc[rt][j][2] - mean1) * rs1 * g0 + b0,
                            (acc[rt][j][3] - mean1) * rs1 * g1 + b1);
        }
    }
}

// ---------------------------------------------------------------------------
extern "C" void kernel_launch(void* const* d_in, const int* in_sizes, int n_in,
                              void* d_out, int out_size) {
    const float* X     = (const float*)d_in[0];
    const float* mask  = (const float*)d_in[1];
    const int*   ridx  = (const int*)d_in[2];
    const int*   chain = (const int*)d_in[3];
    const float* Wpos  = (const float*)d_in[4];
    const float* bpos  = (const float*)d_in[5];
    const float* Wedge = (const float*)d_in[6];
    const float* gam   = (const float*)d_in[7];
    const float* bet   = (const float*)d_in[8];

    float* outE = (float*)d_out;
    size_t nE = (size_t)BB * LL * KNN * ED;
    float* outI = ((size_t)out_size > nE) ? (outE + nE) : nullptr;

    wt_kernel<<<(208 * ED + 255) / 256, 256>>>(Wedge);
    atoms_kernel<<<(BB * LL + 255) / 256, 256>>>(X);
    topk_kernel<<<BB * LL, 256>>>(X, mask, outI);

    static const int smemK3 = DSMW * 4;   // 49152 B (pipeline only)
    cudaFuncSetAttribute(edge_kernel,
                         cudaFuncAttributeMaxDynamicSharedMemorySize, smemK3);
    edge_kernel<<<BB * LL / 2, 256, smemK3>>>(ridx, chain, Wpos, bpos,
                                              gam, bet, outE);
    (void)in_sizes; (void)n_in;
}

// round 10
// speedup vs baseline: 6.2789x; 1.0975x over previous
#include <cuda_runtime.h>
#include <cuda_fp16.h>
#include <cstdint>

#define BB   2
#define LL   2048
#define KNN  48
#define ED   128
#define NCH  13            // 13 K-chunks of 32 fp32 cols = K=416

#define ASTR 20            // A smem row stride in u32 (16 half2 + 4 pad)
#define WSTR 132           // W smem row stride in u32 (128 + 4 pad)
#define AWRD (96 * ASTR)   // words per A stage = 1920
#define WWRD (16 * WSTR)   // words per W stage = 2112 (16 k-pair rows)
#define DSMW (2 * AWRD + 4 * WWRD)   // 12288 words = 49152 B

// scratch (allocation-free rule: __device__ globals)
__device__ float    g_atoms[BB * LL * 15];
__device__ float4   g_ca[BB * LL];    // packed (Ca.xyz, mask) for topk
__device__ int      g_eidx[BB * LL * KNN];
__device__ unsigned g_Wh[208 * ED];   // W as half2 k-pairs: [k/2][n]

__device__ __forceinline__ unsigned smem_u32(const void* p) {
    unsigned a;
    asm("{ .reg .u64 t; cvta.to.shared.u64 t, %1; cvt.u32.u64 %0, t; }"
        : "=r"(a) : "l"(p));
    return a;
}
__device__ __forceinline__ void cp16(unsigned dst, const void* src) {
    asm volatile("cp.async.cg.shared.global [%0], [%1], 16;" :: "r"(dst), "l"(src));
}
__device__ __forceinline__ void cp_commit() {
    asm volatile("cp.async.commit_group;" ::: "memory");
}
__device__ __forceinline__ void cp_wait2() {
    asm volatile("cp.async.wait_group 2;" ::: "memory");
}
__device__ __forceinline__ unsigned packh2(float a, float b) {
    __half2 h = __floats2half2_rn(a, b);
    return *(unsigned*)&h;
}
__device__ __forceinline__ void ldmA(unsigned* a, unsigned addr) {
    asm volatile(
        "ldmatrix.sync.aligned.m8n8.x4.shared.b16 {%0,%1,%2,%3}, [%4];"
        : "=r"(a[0]), "=r"(a[1]), "=r"(a[2]), "=r"(a[3]) : "r"(addr));
}

#define MMA_F16(d, a, b)                                                      \
    asm volatile(                                                             \
        "mma.sync.aligned.m16n8k16.row.col.f32.f16.f16.f32 "                  \
        "{%0,%1,%2,%3}, {%4,%5,%6,%7}, {%8,%9}, {%0,%1,%2,%3};"               \
        : "+f"(d[0]), "+f"(d[1]), "+f"(d[2]), "+f"(d[3])                      \
        : "r"(a[0]), "r"(a[1]), "r"(a[2]), "r"(a[3]), "r"(b[0]), "r"(b[1]))

// ---------------------------------------------------------------------------
// Kernel 0: pack W into half2 k-pairs: g_Wh[kk][n] = (h(W[2kk][n]), h(W[2kk+1][n]))
// ---------------------------------------------------------------------------
__global__ void wt_kernel(const float* __restrict__ W) {
    int idx = blockIdx.x * blockDim.x + threadIdx.x;
    if (idx >= 208 * ED) return;
    int kk = idx / ED, n = idx % ED;
    g_Wh[idx] = packh2(W[(2 * kk) * ED + n], W[(2 * kk + 1) * ED + n]);
}

// ---------------------------------------------------------------------------
// Kernel 1: build atoms[Ca,N,C,O,Cb] per residue + packed (Ca,mask) for topk
// ---------------------------------------------------------------------------
__global__ void atoms_kernel(const float* __restrict__ X,
                             const float* __restrict__ mask) {
    int idx = blockIdx.x * blockDim.x + threadIdx.x;
    if (idx >= BB * LL) return;
    const float* x = X + (size_t)idx * 12;
    float Nx = x[0],  Ny = x[1],  Nz = x[2];
    float Cax = x[3], Cay = x[4], Caz = x[5];
    float Cx = x[6],  Cy = x[7],  Cz = x[8];
    float Ox = x[9],  Oy = x[10], Oz = x[11];

    float bx = Cax - Nx,  by = Cay - Ny,  bz = Caz - Nz;
    float cx = Cx - Cax,  cy = Cy - Cay,  cz = Cz - Caz;
    float ax = by * cz - bz * cy;
    float ay = bz * cx - bx * cz;
    float az = bx * cy - by * cx;
    float Cbx = -0.58273431f * ax + 0.56802827f * bx - 0.54067466f * cx + Cax;
    float Cby = -0.58273431f * ay + 0.56802827f * by - 0.54067466f * cy + Cay;
    float Cbz = -0.58273431f * az + 0.56802827f * bz - 0.54067466f * cz + Caz;

    float* o = g_atoms + (size_t)idx * 15;
    o[0]  = Cax; o[1]  = Cay; o[2]  = Caz;
    o[3]  = Nx;  o[4]  = Ny;  o[5]  = Nz;
    o[6]  = Cx;  o[7]  = Cy;  o[8]  = Cz;
    o[9]  = Ox;  o[10] = Oy;  o[11] = Oz;
    o[12] = Cbx; o[13] = Cby; o[14] = Cbz;

    g_ca[idx] = make_float4(Cax, Cay, Caz, mask[idx]);
}

// ---------------------------------------------------------------------------
// Radix-select helper (warp 0 scans hist[256] for pivot crossing thr)
// ---------------------------------------------------------------------------
__device__ __forceinline__ void scan_pivot(const unsigned* hist, unsigned thr,
                                           unsigned* s_pivot, unsigned* s_base,
                                           int tid) {
    if (tid < 32) {
        unsigned v[8], pre[8], s = 0;
#pragma unroll
        for (int j = 0; j < 8; j++) { v[j] = hist[tid * 8 + j]; pre[j] = s; s += v[j]; }
        unsigned tot = s, x = tot;
#pragma unroll
        for (int off = 1; off < 32; off <<= 1) {
            unsigned y = __shfl_up_sync(0xffffffffu, x, off);
            if (tid >= off) x += y;
        }
        unsigned ex = x - tot;
        if (ex < thr && ex + tot >= thr) {
#pragma unroll
            for (int j = 0; j < 8; j++) {
                unsigned cb = ex + pre[j];
                if (cb < thr && cb + v[j] >= thr) { *s_pivot = tid * 8 + j; *s_base = cb; }
            }
        }
    }
}

// ---------------------------------------------------------------------------
// Kernel 2: top-K via exact 2-level radix select + extraction + bitonic sort
// ---------------------------------------------------------------------------
__global__ void __launch_bounds__(256) topk_kernel(float* __restrict__ outI) {
    __shared__ __align__(16) char sbuf[32768];
    float* cxs = (float*)sbuf;
    float* cys = cxs + LL;
    float* czs = cys + LL;
    float* mms = czs + LL;
    unsigned long long* cand1 = (unsigned long long*)sbuf;            // 16KB
    unsigned long long* cand2 = (unsigned long long*)(sbuf + 16384);  // 16KB
    __shared__ unsigned hist[256];
    __shared__ unsigned long long win[64];
    __shared__ unsigned s_nwin, s_nc1, s_nc2, s_pivot, s_base;
    __shared__ float wmaxs[8];
    __shared__ float s_dmax;

    int b   = blockIdx.x >> 11;
    int i   = blockIdx.x & (LL - 1);
    int tid = threadIdx.x;
    int lane = tid & 31, wid = tid >> 5;

    for (int t = tid; t < LL; t += 256) {
        float4 v = g_ca[b * LL + t];
        cxs[t] = v.x; cys[t] = v.y; czs[t] = v.z; mms[t] = v.w;
    }
    __syncthreads();

    float xi = cxs[i], yi = cys[i], zi = czs[i], mi = mms[i];
    float dv[8], m2v[8];
    float dmax = 0.0f;
#pragma unroll
    for (int u = 0; u < 8; u++) {
        int j = tid * 8 + u;
        // exact fp32 op order, no fma-contraction, IEEE sqrt (matches XLA)
        float dx = __fsub_rn(cxs[j], xi);
        float dy = __fsub_rn(cys[j], yi);
        float dz = __fsub_rn(czs[j], zi);
        float s  = __fadd_rn(__fadd_rn(__fmul_rn(dx, dx), __fmul_rn(dy, dy)),
                             __fmul_rn(dz, dz));
        float dd  = __fsqrt_rn(__fadd_rn(s, 1e-6f));
        float mij = __fmul_rn(mi, mms[j]);
        dv[u]  = __fmul_rn(mij, dd);
        m2v[u] = mij;
        dmax = fmaxf(dmax, dv[u]);
    }
#pragma unroll
    for (int off = 16; off > 0; off >>= 1)
        dmax = fmaxf(dmax, __shfl_xor_sync(0xffffffffu, dmax, off));
    if (lane == 0) wmaxs[wid] = dmax;
    __syncthreads();
    if (tid == 0) {
        float m = wmaxs[0];
        for (int w = 1; w < 8; w++) m = fmaxf(m, wmaxs[w]);
        s_dmax = m;
    }
    __syncthreads();
    float dmx = s_dmax;

    unsigned long long k[8];
#pragma unroll
    for (int u = 0; u < 8; u++) {
        float adj = __fadd_rn(dv[u], __fmul_rn(__fsub_rn(1.0f, m2v[u]), dmx));
        k[u] = ((unsigned long long)__float_as_uint(adj) << 32) |
               (unsigned)(tid * 8 + u);
    }
    __syncthreads();

    hist[tid] = 0;
    if (tid == 0) { s_nwin = 0; s_nc1 = 0; s_nc2 = 0; }
    __syncthreads();
#pragma unroll
    for (int u = 0; u < 8; u++)
        atomicAdd(&hist[(unsigned)(k[u] >> 56)], 1u);
    __syncthreads();
    scan_pivot(hist, 48u, &s_pivot, &s_base, tid);
    __syncthreads();
    unsigned p1 = s_pivot, base1 = s_base;
#pragma unroll
    for (int u = 0; u < 8; u++) {
        unsigned bn = (unsigned)(k[u] >> 56);
        if (bn < p1)       win[atomicAdd(&s_nwin, 1u)]   = k[u];
        else if (bn == p1) cand1[atomicAdd(&s_nc1, 1u)]  = k[u];
    }
    __syncthreads();

    unsigned need = 48u - base1;
    hist[tid] = 0;
    __syncthreads();
    unsigned nc1 = s_nc1;
    for (unsigned t = tid; t < nc1; t += 256)
        atomicAdd(&hist[(unsigned)(cand1[t] >> 48) & 255u], 1u);
    __syncthreads();
    scan_pivot(hist, need, &s_pivot, &s_base, tid);
    __syncthreads();
    unsigned p2 = s_pivot;
    for (unsigned t = tid; t < nc1; t += 256) {
        unsigned long long v = cand1[t];
        unsigned bn = (unsigned)(v >> 48) & 255u;
        if (bn < p2)       win[atomicAdd(&s_nwin, 1u)]  = v;
        else if (bn == p2) cand2[atomicAdd(&s_nc2, 1u)] = v;
    }
    __syncthreads();

    if (wid == 0) {
        int m2 = (int)s_nc2;
        int nw = (int)s_nwin;
        int rem = 48 - nw;
        for (int r = 0; r < rem; r++) {
            unsigned long long best = ~0ull; int bp = -1;
            for (int t = lane; t < m2; t += 32) {
                unsigned long long v = cand2[t];
                if (v < best) { best = v; bp = t; }
            }
#pragma unroll
            for (int off = 16; off > 0; off >>= 1) {
                unsigned long long o = __shfl_xor_sync(0xffffffffu, best, off);
                int op = __shfl_xor_sync(0xffffffffu, bp, off);
                if (o < best) { best = o; bp = op; }
            }
            if (lane == 0) { win[nw + r] = best; cand2[bp] = ~0ull; }
            __syncwarp();
        }
    }
    if (tid >= 48 && tid < 64) win[tid] = ~0ull;
    __syncthreads();

    if (wid == 0) {
        unsigned long long a0 = win[2 * lane], a1 = win[2 * lane + 1];
#pragma unroll
        for (int kk = 2; kk <= 64; kk <<= 1) {
#pragma unroll
            for (int j = kk >> 1; j >= 1; j >>= 1) {
                bool up = ((2 * lane) & kk) == 0;
                if (j == 1) {
                    if (up ? (a0 > a1) : (a0 < a1)) {
                        unsigned long long t = a0; a0 = a1; a1 = t;
                    }
                } else {
                    int d = j >> 1;
                    bool lower = (lane & d) == 0;
                    unsigned long long q0 = __shfl_xor_sync(0xffffffffu, a0, d);
                    unsigned long long q1 = __shfl_xor_sync(0xffffffffu, a1, d);
                    bool keepmin = (up == lower);
                    a0 = keepmin ? (a0 < q0 ? a0 : q0) : (a0 > q0 ? a0 : q0);
                    a1 = keepmin ? (a1 < q1 ? a1 : q1) : (a1 > q1 ? a1 : q1);
                }
            }
        }
        size_t baseo = (size_t)(b * LL + i) * KNN;
        int r0 = 2 * lane, r1 = 2 * lane + 1;
        if (r0 < KNN) {
            int j = (int)(unsigned)(a0 & 0xffffffffull);
            g_eidx[baseo + r0] = j;
            if (outI) outI[baseo + r0] = (float)j;
        }
        if (r1 < KNN) {
            int j = (int)(unsigned)(a1 & 0xffffffffull);
            g_eidx[baseo + r1] = j;
            if (outI) outI[baseo + r1] = (float)j;
        }
    }
}

// ---------------------------------------------------------------------------
// Kernel 3 (hot): 2 nodes per CTA (96x128). fp16 m16n8k16 MMA (fp32 accum).
// A fragments via ldmatrix.x4 (1/4 issue slots), features stored as uint4.
// Direct-store LN epilogue. __launch_bounds__(256,3) -> 3 CTAs/SM.
// ---------------------------------------------------------------------------
__global__ void __launch_bounds__(256, 3) edge_kernel(
    const int* __restrict__ ridx, const int* __restrict__ chain,
    const float* __restrict__ Wpos, const float* __restrict__ bpos,
    const float* __restrict__ gamma_, const float* __restrict__ beta_,
    float* __restrict__ outE) {
    extern __shared__ unsigned dsm[];
    __shared__ float ssat[2 * 15];
    __shared__ float snat[96 * 15];
    __shared__ float gam[ED], bet[ED];
    __shared__ float bposs[16];
    __shared__ int   eidx_s[96];
    __shared__ int   dcls[96];
    __shared__ float2 psum[96][4];     // per-(row, colgroup) partial (sum, sumsq)

    int tid  = threadIdx.x;
    int wid  = tid >> 5;
    int lane = tid & 31;
    int gid  = lane >> 2, tg = lane & 3;
    int node0 = 2 * blockIdx.x;
    int b = node0 >> 11;

    unsigned smA = smem_u32(dsm);
    unsigned smW = smA + 2 * AWRD * 4;

    if (tid < ED) { gam[tid] = gamma_[tid]; bet[tid] = beta_[tid]; }
    if (tid < 16) bposs[tid] = bpos[tid];
    if (tid < 96) eidx_s[tid] = g_eidx[(size_t)node0 * KNN + tid];
    if (tid >= 128 && tid < 158) ssat[tid - 128] = g_atoms[(size_t)node0 * 15 + (tid - 128)];
    __syncthreads();

    if (tid < 96) {
        int nl = tid / KNN;
        int j  = eidx_s[tid];
        int ng = node0 + nl;
        int off  = ridx[ng] - ridx[b * LL + j];
        int same = (chain[ng] == chain[b * LL + j]);
        int d = off + 32;
        d = d < 0 ? 0 : (d > 64 ? 64 : d);
        dcls[tid] = same ? d : 65;
    }
    for (int t = tid; t < 96 * 15; t += 256) {
        int n = t / 15, c = t % 15;
        snat[t] = g_atoms[(size_t)(b * LL + eidx_s[n]) * 15 + c];
    }

    // prologue: W chunks 0,1 into ring stages 0,1 (8KB each, 2 cp16/thread)
#pragma unroll
    for (int q = 0; q < 2; q++) {
        unsigned bst = smW + (unsigned)(q & 3) * WWRD * 4;
#pragma unroll
        for (int e = 0; e < 2; e++) {
            int idx = tid + e * 256;            // 0..511
            int r = idx >> 5, g = idx & 31;     // k-pair row 0..15, granule 0..31
            cp16(bst + (unsigned)(r * WSTR + g * 4) * 4,
                 g_Wh + (size_t)(q * 16 + r) * ED + g * 4);
        }
        cp_commit();
    }
    __syncthreads();   // snat/ssat/dcls visible before feature compute

    // prologue: features chunk 0 (positional + pair 0) into A stage 0
    {
        uint4* Ab = (uint4*)dsm;
        if (tid < 96) {
            int row = tid, dc = dcls[row];
            unsigned w[8];
#pragma unroll
            for (int q = 0; q < 8; q++)
                w[q] = packh2(Wpos[dc * 16 + 2 * q]     + bposs[2 * q],
                              Wpos[dc * 16 + 2 * q + 1] + bposs[2 * q + 1]);
            Ab[(row * ASTR) >> 2]       = make_uint4(w[0], w[1], w[2], w[3]);
            Ab[(row * ASTR + 4) >> 2]   = make_uint4(w[4], w[5], w[6], w[7]);
        } else if (tid < 192) {
            int row = tid - 96;                 // pair 0 (Ca-Ca)
            int nl = row / KNN;
            float dx = ssat[nl * 15 + 0] - snat[row * 15 + 0];
            float dy = ssat[nl * 15 + 1] - snat[row * 15 + 1];
            float dz = ssat[nl * 15 + 2] - snat[row * 15 + 2];
            float Dp = sqrtf(dx * dx + dy * dy + dz * dz + 1e-6f);
            unsigned w[8];
#pragma unroll
            for (int q = 0; q < 8; q++) {
                float mu0 = 2.0f + (20.0f / 15.0f) * (float)(2 * q);
                float mu1 = 2.0f + (20.0f / 15.0f) * (float)(2 * q + 1);
                float z0 = (Dp - mu0) * 0.8f, z1 = (Dp - mu1) * 0.8f;
                w[q] = packh2(__expf(-z0 * z0), __expf(-z1 * z1));
            }
            Ab[(row * ASTR + 8) >> 2]   = make_uint4(w[0], w[1], w[2], w[3]);
            Ab[(row * ASTR + 12) >> 2]  = make_uint4(w[4], w[5], w[6], w[7]);
        }
    }

    float acc[3][4][4];
#pragma unroll
    for (int rt = 0; rt < 3; rt++)
#pragma unroll
        for (int j = 0; j < 4; j++)
#pragma unroll
            for (int c = 0; c < 4; c++) acc[rt][j][c] = 0.0f;

    int rg = wid >> 2, cg = wid & 3;
    int rowbase = rg * 48;
    int colbase = cg * 32;
    // ldmatrix lane address component: row = rowbase + (lane&15), koff = (lane>>4)*4
    unsigned lmBase = (unsigned)(((rowbase + (lane & 15)) * ASTR + ((lane >> 4) << 2)) * 4);

    for (int c = 0; c < NCH; c++) {
        // ---- issue W chunk c+2 into ring stage (c+2)&3 ----
        if (c + 2 < NCH) {
            int q = c + 2;
            unsigned bst = smW + (unsigned)(q & 3) * WWRD * 4;
#pragma unroll
            for (int e = 0; e < 2; e++) {
                int idx = tid + e * 256;
                int r = idx >> 5, g = idx & 31;
                cp16(bst + (unsigned)(r * WSTR + g * 4) * 4,
                     g_Wh + (size_t)(q * 16 + r) * ED + g * 4);
            }
        }
        cp_commit();
        cp_wait2();              // W chunk c landed
        __syncthreads();         // A(c) features + W(c) visible; orders
                                 // MMA(c-1) reads before features(c+1) writes

        // ---- MMA on chunk c: 2 k16 steps (reads A[c&1], W[c&3]) ----
        unsigned aBase = smA + (unsigned)((c & 1) * AWRD * 4) + lmBase;
        unsigned* Wb = dsm + 2 * AWRD + (c & 3) * WWRD;
#pragma unroll
        for (int s = 0; s < 2; s++) {
            int kb = s * 8;      // u32 (half2) column base
            unsigned a[3][4];
#pragma unroll
            for (int rt = 0; rt < 3; rt++)
                ldmA(a[rt], aBase + (unsigned)((rt * 16 * ASTR + kb) * 4));
            unsigned bf[4][2];
#pragma unroll
            for (int j = 0; j < 4; j++) {
                bf[j][0] = Wb[(kb + tg) * WSTR + colbase + j * 8 + gid];
                bf[j][1] = Wb[(kb + tg + 4) * WSTR + colbase + j * 8 + gid];
            }
#pragma unroll
            for (int rt = 0; rt < 3; rt++)
#pragma unroll
                for (int j = 0; j < 4; j++)
                    MMA_F16(acc[rt][j], a[rt], bf[j]);
        }

        // ---- overlap: compute features chunk c+1 into A[(c+1)&1] ----
        if (c + 1 < NCH && tid < 192) {
            uint4* An = (uint4*)(dsm + ((c + 1) & 1) * AWRD);
            int pi = tid / 96, row = tid % 96;
            int nl = row / KNN;
            int p  = 2 * (c + 1) - 1 + pi;         // pair 1..24
            int a1 = p / 5, a2 = p % 5;
            float dx = ssat[nl * 15 + a1 * 3 + 0] - snat[row * 15 + a2 * 3 + 0];
            float dy = ssat[nl * 15 + a1 * 3 + 1] - snat[row * 15 + a2 * 3 + 1];
            float dz = ssat[nl * 15 + a1 * 3 + 2] - snat[row * 15 + a2 * 3 + 2];
            float Dp = sqrtf(dx * dx + dy * dy + dz * dz + 1e-6f);
            int cb = 8 * pi;
            unsigned w[8];
#pragma unroll
            for (int q = 0; q < 8; q++) {
                float mu0 = 2.0f + (20.0f / 15.0f) * (float)(2 * q);
                float mu1 = 2.0f + (20.0f / 15.0f) * (float)(2 * q + 1);
                float z0 = (Dp - mu0) * 0.8f, z1 = (Dp - mu1) * 0.8f;
                w[q] = packh2(__expf(-z0 * z0), __expf(-z1 * z1));
            }
            An[(row * ASTR + cb) >> 2]     = make_uint4(w[0], w[1], w[2], w[3]);
            An[(row * ASTR + cb + 4) >> 2] = make_uint4(w[4], w[5], w[6], w[7]);
        }
    }

    // ---- epilogue: per-row partials across the 4 colgroup warps ----
#pragma unroll
    for (int rt = 0; rt < 3; rt++) {
        float s0 = 0.f, q0 = 0.f, s1 = 0.f, q1 = 0.f;
#pragma unroll
        for (int j = 0; j < 4; j++) {
            s0 += acc[rt][j][0] + acc[rt][j][1];
            q0 += acc[rt][j][0] * acc[rt][j][0] + acc[rt][j][1] * acc[rt][j][1];
            s1 += acc[rt][j][2] + acc[rt][j][3];
            q1 += acc[rt][j][2] * acc[rt][j][2] + acc[rt][j][3] * acc[rt][j][3];
        }
#pragma unroll
        for (int m = 1; m <= 2; m <<= 1) {
            s0 += __shfl_xor_sync(0xffffffffu, s0, m);
            q0 += __shfl_xor_sync(0xffffffffu, q0, m);
            s1 += __shfl_xor_sync(0xffffffffu, s1, m);
            q1 += __shfl_xor_sync(0xffffffffu, q1, m);
        }
        if (tg == 0) {
            int r0 = rowbase + rt * 16 + gid;
            psum[r0][cg]     = make_float2(s0, q0);
            psum[r0 + 8][cg] = make_float2(s1, q1);
        }
    }
    __syncthreads();

    // ---- LN in registers + direct float2 stores to gmem ----
    size_t obase = (size_t)node0 * KNN * ED;
#pragma unroll
    for (int rt = 0; rt < 3; rt++) {
        int r0 = rowbase + rt * 16 + gid;
        float2 pa0 = psum[r0][0], pa1 = psum[r0][1];
        float2 pa2 = psum[r0][2], pa3 = psum[r0][3];
        float2 pb0 = psum[r0 + 8][0], pb1 = psum[r0 + 8][1];
        float2 pb2 = psum[r0 + 8][2], pb3 = psum[r0 + 8][3];
        float mean0 = (pa0.x + pa1.x + pa2.x + pa3.x) * (1.0f / 128.0f);
        float var0  = (pa0.y + pa1.y + pa2.y + pa3.y) * (1.0f / 128.0f) - mean0 * mean0;
        float rs0   = rsqrtf(var0 + 1e-5f);
        float mean1 = (pb0.x + pb1.x + pb2.x + pb3.x) * (1.0f / 128.0f);
        float var1  = (pb0.y + pb1.y + pb2.y + pb3.y) * (1.0f / 128.0f) - mean1 * mean1;
        float rs1   = rsqrtf(var1 + 1e-5f);
        float* dst0 = outE + obase + (size_t)r0 * ED;
        float* dst1 = dst0 + 8 * ED;
#pragma unroll
        for (int j = 0; j < 4; j++) {
            int col = colbase + j * 8 + 2 * tg;
            float g0 = gam[col], g1 = gam[col + 1];
            float b0 = bet[col], b1 = bet[col + 1];
            *(float2*)(dst0 + col) =
                make_float2((acc[rt][j][0] - mean0) * rs0 * g0 + b0,
                            (acc[rt][j][1] - mean0) * rs0 * g1 + b1);
            *(float2*)(dst1 + col) =
                make_float2((acc[rt][j][2] - mean1) * rs1 * g0 + b0,
                            (acc[rt][j][3] - mean1) * rs1 * g1 + b1);
        }
    }
}

// ---------------------------------------------------------------------------
extern "C" void kernel_launch(void* const* d_in, const int* in_sizes, int n_in,
                              void* d_out, int out_size) {
    const float* X     = (const float*)d_in[0];
    const float* mask  = (const float*)d_in[1];
    const int*   ridx  = (const int*)d_in[2];
    const int*   chain = (const int*)d_in[3];
    const float* Wpos  = (const float*)d_in[4];
    const float* bpos  = (const float*)d_in[5];
    const float* Wedge = (const float*)d_in[6];
    const float* gam   = (const float*)d_in[7];
    const float* bet   = (const float*)d_in[8];

    float* outE = (float*)d_out;
    size_t nE = (size_t)BB * LL * KNN * ED;
    float* outI = ((size_t)out_size > nE) ? (outE + nE) : nullptr;

    wt_kernel<<<(208 * ED + 255) / 256, 256>>>(Wedge);
    atoms_kernel<<<(BB * LL + 255) / 256, 256>>>(X, mask);
    topk_kernel<<<BB * LL, 256>>>(outI);

    static const int smemK3 = DSMW * 4;   // 49152 B (pipeline only)
    cudaFuncSetAttribute(edge_kernel,
                         cudaFuncAttributeMaxDynamicSharedMemorySize, smemK3);
    edge_kernel<<<BB * LL / 2, 256, smemK3>>>(ridx, chain, Wpos, bpos,
                                              gam, bet, outE);
    (void)in_sizes; (void)n_in;
}